// round 1
// baseline (speedup 1.0000x reference)
#include <cuda_runtime.h>
#include <cstdint>
#include <math.h>

using u64 = unsigned long long;

// ---------------------------------------------------------------------------
// Packed fp32x2 FMA (Blackwell FFMA2) helpers
// ---------------------------------------------------------------------------
__device__ __forceinline__ void ffma2(u64 &d, u64 a, u64 b) {
    asm("fma.rn.f32x2 %0, %1, %2, %0;" : "+l"(d) : "l"(a), "l"(b));
}
__device__ __forceinline__ float2 unpk(u64 v) {
    float2 r;
    asm("mov.b64 {%0, %1}, %2;" : "=f"(r.x), "=f"(r.y) : "l"(v));
    return r;
}

// ---------------------------------------------------------------------------
// Scratch (device globals: allocation-free per harness rules)
// ---------------------------------------------------------------------------
static const int BATCH = 16;
static const int CCH   = 256;    // attention channel dim
static const int NSP   = 4096;   // spatial dim H*W
static const int NSPLIT = 4;     // split-K for logits

__device__ float g_img [(size_t)BATCH * CCH * NSP];            // 64 MiB
__device__ float g_kv  [(size_t)BATCH * CCH * NSP];            // 64 MiB
__device__ float g_part[(size_t)NSPLIT * BATCH * CCH * CCH];   // 16 MiB
__device__ float g_attn[(size_t)BATCH * CCH * CCH];            //  4 MiB

// ---------------------------------------------------------------------------
// NN SGEMM: C[b] = A[b] (MxK, row-major) @ B[b] (KxN, row-major)
// 128x128 block tile, BK=16, 256 threads, 8x8 microtile via FFMA2.
// A tile stored DUPLICATED in smem ({a,a} pairs) so the inner loop has zero
// duplication MOVs; A-fragment LDS.64 reads broadcast (2 addrs/warp).
// Optional epilogue: C = gamma*acc + R (scale-residual), may alias R==C.
// Requires: M%128==0, N%128==0, K%16==0.
// ---------------------------------------------------------------------------
template <bool RESID>
__global__ __launch_bounds__(256, 2)
void sgemm_nn(const float* __restrict__ Ag, const float* __restrict__ Bg,
              float* __restrict__ Cg, const float* __restrict__ Rg,
              const float* __restrict__ gamma,
              int M, int N, int K, long sA, long sB, long sC)
{
    __shared__ __align__(16) float Asd[16][258];  // duplicated+transposed A
    __shared__ __align__(16) float Bs [16][128];

    const int bz = blockIdx.z;
    const float* A = Ag + (size_t)bz * (size_t)sA;
    const float* B = Bg + (size_t)bz * (size_t)sB;
    float*       C = Cg + (size_t)bz * (size_t)sC;
    const float* R = RESID ? (Rg + (size_t)bz * (size_t)sC) : nullptr;

    const int m0 = blockIdx.y * 128;
    const int n0 = blockIdx.x * 128;
    const int tid = threadIdx.x;
    const int tr = tid >> 4;   // 0..15 (row group of 8)
    const int tc = tid & 15;   // 0..15 (col group of 8)

    u64 acc[8][4];
    #pragma unroll
    for (int i = 0; i < 8; i++)
        #pragma unroll
        for (int j = 0; j < 4; j++) acc[i][j] = 0ull;

    for (int kt = 0; kt < K; kt += 16) {
        #pragma unroll
        for (int t = 0; t < 2; t++) {
            int idx = tid + t * 256;
            // A tile: 128 rows x 16 k, float4 per (row, k-quad), dup-store
            int r  = idx >> 2;
            int c4 = (idx & 3) * 4;
            float4 v = *(const float4*)(A + (size_t)(m0 + r) * K + kt + c4);
            Asd[c4 + 0][2 * r] = v.x; Asd[c4 + 0][2 * r + 1] = v.x;
            Asd[c4 + 1][2 * r] = v.y; Asd[c4 + 1][2 * r + 1] = v.y;
            Asd[c4 + 2][2 * r] = v.z; Asd[c4 + 2][2 * r + 1] = v.z;
            Asd[c4 + 3][2 * r] = v.w; Asd[c4 + 3][2 * r + 1] = v.w;
            // B tile: 16 rows x 128 cols
            int rb = idx >> 5;
            int cb = (idx & 31) * 4;
            *(float4*)&Bs[rb][cb] =
                *(const float4*)(B + (size_t)(kt + rb) * N + n0 + cb);
        }
        __syncthreads();

        #pragma unroll
        for (int k = 0; k < 16; k++) {
            u64 a[8];
            const u64* ap = (const u64*)&Asd[k][tr * 16];
            #pragma unroll
            for (int i = 0; i < 8; i++) a[i] = ap[i];
            ulonglong2 q0 = *(const ulonglong2*)&Bs[k][tc * 8];
            ulonglong2 q1 = *(const ulonglong2*)&Bs[k][tc * 8 + 4];
            u64 b0 = q0.x, b1 = q0.y, b2 = q1.x, b3 = q1.y;
            #pragma unroll
            for (int i = 0; i < 8; i++) {
                ffma2(acc[i][0], a[i], b0);
                ffma2(acc[i][1], a[i], b1);
                ffma2(acc[i][2], a[i], b2);
                ffma2(acc[i][3], a[i], b3);
            }
        }
        __syncthreads();
    }

    const float g = RESID ? gamma[0] : 0.0f;
    #pragma unroll
    for (int i = 0; i < 8; i++) {
        size_t off = (size_t)(m0 + tr * 8 + i) * N + n0 + tc * 8;
        float o[8];
        #pragma unroll
        for (int j = 0; j < 4; j++) {
            float2 p = unpk(acc[i][j]);
            o[2 * j] = p.x; o[2 * j + 1] = p.y;
        }
        if (RESID) {
            float4 r0 = *(const float4*)(R + off);
            float4 r1 = *(const float4*)(R + off + 4);
            o[0] = g * o[0] + r0.x; o[1] = g * o[1] + r0.y;
            o[2] = g * o[2] + r0.z; o[3] = g * o[3] + r0.w;
            o[4] = g * o[4] + r1.x; o[5] = g * o[5] + r1.y;
            o[6] = g * o[6] + r1.z; o[7] = g * o[7] + r1.w;
        }
        *(float4*)(C + off)     = make_float4(o[0], o[1], o[2], o[3]);
        *(float4*)(C + off + 4) = make_float4(o[4], o[5], o[6], o[7]);
    }
}

// ---------------------------------------------------------------------------
// NT logits GEMM: P[s][b][m][n] = sum_{k in split s} Q[b][m][k] * KV[b][n][k]
// 64x64 tile, BK=32, 4x4 microtile via FFMA2, split-K=4 (deterministic
// partial buffers, no float atomics). K contiguous in both operands.
// ---------------------------------------------------------------------------
__global__ __launch_bounds__(256)
void attn_logits(const float* __restrict__ Qg, const float* __restrict__ Kg,
                 float* __restrict__ P)
{
    const int KC = NSP / NSPLIT;          // 1024
    const int b  = blockIdx.z >> 2;
    const int s  = blockIdx.z & 3;
    const float* A  = Qg + (size_t)b * CCH * NSP + (size_t)s * KC;
    const float* Bv = Kg + (size_t)b * CCH * NSP + (size_t)s * KC;

    __shared__ __align__(16) float Asd[32][132];  // duplicated A rows
    __shared__ __align__(16) float Bs [32][68];   // transposed KV tile

    const int m0 = blockIdx.y * 64;
    const int n0 = blockIdx.x * 64;
    const int tid = threadIdx.x;
    const int tr = tid >> 4, tc = tid & 15;

    u64 acc[4][2];
    #pragma unroll
    for (int i = 0; i < 4; i++) { acc[i][0] = 0ull; acc[i][1] = 0ull; }

    for (int kt = 0; kt < KC; kt += 32) {
        #pragma unroll
        for (int t = 0; t < 2; t++) {
            int idx = tid + t * 256;
            int r  = idx >> 3;            // 0..63
            int c4 = (idx & 7) * 4;       // 0..28
            float4 va = *(const float4*)(A + (size_t)(m0 + r) * NSP + kt + c4);
            Asd[c4 + 0][2 * r] = va.x; Asd[c4 + 0][2 * r + 1] = va.x;
            Asd[c4 + 1][2 * r] = va.y; Asd[c4 + 1][2 * r + 1] = va.y;
            Asd[c4 + 2][2 * r] = va.z; Asd[c4 + 2][2 * r + 1] = va.z;
            Asd[c4 + 3][2 * r] = va.w; Asd[c4 + 3][2 * r + 1] = va.w;
            float4 vb = *(const float4*)(Bv + (size_t)(n0 + r) * NSP + kt + c4);
            Bs[c4 + 0][r] = vb.x; Bs[c4 + 1][r] = vb.y;
            Bs[c4 + 2][r] = vb.z; Bs[c4 + 3][r] = vb.w;
        }
        __syncthreads();

        #pragma unroll
        for (int k = 0; k < 32; k++) {
            const u64* ap = (const u64*)&Asd[k][tr * 8];
            u64 a0 = ap[0], a1 = ap[1], a2 = ap[2], a3 = ap[3];
            ulonglong2 q = *(const ulonglong2*)&Bs[k][tc * 4];
            ffma2(acc[0][0], a0, q.x); ffma2(acc[0][1], a0, q.y);
            ffma2(acc[1][0], a1, q.x); ffma2(acc[1][1], a1, q.y);
            ffma2(acc[2][0], a2, q.x); ffma2(acc[2][1], a2, q.y);
            ffma2(acc[3][0], a3, q.x); ffma2(acc[3][1], a3, q.y);
        }
        __syncthreads();
    }

    size_t base = (size_t)(s * BATCH + b) * CCH * CCH;
    #pragma unroll
    for (int i = 0; i < 4; i++) {
        float2 p0 = unpk(acc[i][0]);
        float2 p1 = unpk(acc[i][1]);
        *(float4*)(P + base + (size_t)(m0 + tr * 4 + i) * CCH + n0 + tc * 4) =
            make_float4(p0.x, p0.y, p1.x, p1.y);
    }
}

// ---------------------------------------------------------------------------
// Softmax over rows of 256: sums the 4 split-K partials, then softmax.
// One block (256 threads) per (b, c) row.
// ---------------------------------------------------------------------------
__global__ __launch_bounds__(256)
void softmax_rows(const float* __restrict__ P, float* __restrict__ A)
{
    const size_t RS = (size_t)BATCH * CCH * CCH;
    const int row = blockIdx.x;          // b*256 + c
    const int tid = threadIdx.x;
    size_t base = (size_t)row * CCH + tid;
    float x = P[base] + P[RS + base] + P[2 * RS + base] + P[3 * RS + base];

    __shared__ float red[256];
    red[tid] = x;
    __syncthreads();
    for (int o = 128; o > 0; o >>= 1) {
        if (tid < o) red[tid] = fmaxf(red[tid], red[tid + o]);
        __syncthreads();
    }
    float mx = red[0];
    __syncthreads();
    float e = expf(x - mx);
    red[tid] = e;
    __syncthreads();
    for (int o = 128; o > 0; o >>= 1) {
        if (tid < o) red[tid] += red[tid + o];
        __syncthreads();
    }
    float inv = 1.0f / red[0];
    A[(size_t)row * CCH + tid] = e * inv;
}

// ---------------------------------------------------------------------------
// Launch
// ---------------------------------------------------------------------------
extern "C" void kernel_launch(void* const* d_in, const int* in_sizes, int n_in,
                              void* d_out, int out_size)
{
    const float* x1    = (const float*)d_in[0];  // [16,512,64,64]
    const float* x2    = (const float*)d_in[1];  // [16,320,64,64]
    const float* w_img = (const float*)d_in[2];  // [256,512]
    const float* w_txt = (const float*)d_in[3];  // [256,320]
    const float* w_out = (const float*)d_in[4];  // [512,256]
    const float* gamma = (const float*)d_in[5];  // [1]
    float* out = (float*)d_out;                  // [16,512,64,64]

    float *img, *kv, *part, *attn;
    cudaGetSymbolAddress((void**)&img,  g_img);
    cudaGetSymbolAddress((void**)&kv,   g_kv);
    cudaGetSymbolAddress((void**)&part, g_part);
    cudaGetSymbolAddress((void**)&attn, g_attn);

    // 1) img = w_img @ x1   (per batch: 256x4096, K=512)
    sgemm_nn<false><<<dim3(32, 2, 16), 256>>>(
        w_img, x1, img, nullptr, nullptr,
        256, 4096, 512, 0L, 512L * 4096, 256L * 4096);

    // 2) kv = w_txt @ x2    (per batch: 256x4096, K=320)
    sgemm_nn<false><<<dim3(32, 2, 16), 256>>>(
        w_txt, x2, kv, nullptr, nullptr,
        256, 4096, 320, 0L, 320L * 4096, 256L * 4096);

    // 3) logits partials: P[s][b] = Q Ksplit-chunk of (img @ kv^T)
    attn_logits<<<dim3(4, 4, 16 * NSPLIT), 256>>>(img, kv, part);

    // 4) softmax over last dim (sums split-K partials)
    softmax_rows<<<16 * 256, 256>>>(part, attn);

    // 5) t = gamma * (attn @ kv) + img   (in-place into g_img)
    sgemm_nn<true><<<dim3(32, 2, 16), 256>>>(
        attn, kv, img, img, gamma,
        256, 4096, 256, 256L * 256, 256L * 4096, 256L * 4096);

    // 6) out = w_out @ t    (per batch: 512x4096, K=256)
    sgemm_nn<false><<<dim3(32, 4, 16), 256>>>(
        w_out, img, out, nullptr, nullptr,
        512, 4096, 256, 0L, 256L * 4096, 512L * 4096);
}

// round 3
// speedup vs baseline: 2.2774x; 2.2774x over previous
#include <cuda_runtime.h>
#include <cuda_fp16.h>
#include <math.h>

using u32 = unsigned int;

// ===========================================================================
// Problem constants
// ===========================================================================
static const int BATCH  = 16;
static const int CCH    = 256;
static const int NSP    = 4096;
static const int NSPLIT = 8;     // split-K for logits GEMM

// ===========================================================================
// Device scratch (allocation-free). fp16 hi/lo split operand copies.
// ===========================================================================
__device__ __half g_x1Th[(size_t)BATCH * NSP * 512];
__device__ __half g_x1Tl[(size_t)BATCH * NSP * 512];
__device__ __half g_x2Th[(size_t)BATCH * NSP * 320];
__device__ __half g_x2Tl[(size_t)BATCH * NSP * 320];
__device__ __half g_wih[256 * 512], g_wil[256 * 512];
__device__ __half g_wth[256 * 320], g_wtl[256 * 320];
__device__ __half g_woh[512 * 256], g_wol[512 * 256];
__device__ float  g_img [(size_t)BATCH * CCH * NSP];
__device__ __half g_imgh[(size_t)BATCH * CCH * NSP];
__device__ __half g_imgl[(size_t)BATCH * CCH * NSP];
__device__ __half g_kvh [(size_t)BATCH * CCH * NSP];
__device__ __half g_kvl [(size_t)BATCH * CCH * NSP];
__device__ __half g_kvTh[(size_t)BATCH * NSP * CCH];
__device__ __half g_kvTl[(size_t)BATCH * NSP * CCH];
__device__ __half g_tTh [(size_t)BATCH * NSP * CCH];
__device__ __half g_tTl [(size_t)BATCH * NSP * CCH];
__device__ float  g_part[(size_t)NSPLIT * BATCH * CCH * CCH];
__device__ __half g_atth[(size_t)BATCH * CCH * CCH];
__device__ __half g_attl[(size_t)BATCH * CCH * CCH];

// ===========================================================================
// PTX helpers (all base-target ISA: cp.async / ldmatrix / mma.sync)
// ===========================================================================
__device__ __forceinline__ u32 smem_u32(const void* p) {
    u32 a;
    asm("{ .reg .u64 t; cvta.to.shared.u64 t, %1; cvt.u32.u64 %0, t; }"
        : "=r"(a) : "l"(p));
    return a;
}
__device__ __forceinline__ void cp16(u32 dst, const void* src) {
    asm volatile("cp.async.cg.shared.global [%0], [%1], 16;"
                 :: "r"(dst), "l"(src) : "memory");
}
__device__ __forceinline__ void cp_commit() {
    asm volatile("cp.async.commit_group;" ::: "memory");
}
template <int N>
__device__ __forceinline__ void cp_wait() {
    asm volatile("cp.async.wait_group %0;" :: "n"(N) : "memory");
}
#define LDMX4(d0, d1, d2, d3, addr) \
    asm volatile("ldmatrix.sync.aligned.m8n8.x4.shared.b16 {%0,%1,%2,%3},[%4];" \
                 : "=r"(d0), "=r"(d1), "=r"(d2), "=r"(d3) : "r"(addr))
#define MMA16816(c, a, b0, b1) \
    asm volatile("mma.sync.aligned.m16n8k16.row.col.f32.f16.f16.f32 " \
                 "{%0,%1,%2,%3},{%4,%5,%6,%7},{%8,%9},{%0,%1,%2,%3};" \
                 : "+f"((c)[0]), "+f"((c)[1]), "+f"((c)[2]), "+f"((c)[3]) \
                 : "r"((a)[0]), "r"((a)[1]), "r"((a)[2]), "r"((a)[3]), \
                   "r"(b0), "r"(b1))

// ===========================================================================
// Unified NT fp16x2 GEMM (3-pass Markidis split, fp32 accumulate).
// D[m,n] = sum_k A[m,k]*B[n,k]; A,B given as pre-split hi/lo fp16, K-major.
// CTA tile 128x128, BK=32, 8 warps (2x4), warp tile 64x32, 3-stage cp.async.
// RESID: v = gamma*acc + R[m,n].
// WN: write fp32 C[m,n].  WH: write hi/lo fp16 at [m,n].  WHT: at [n,m].
// ===========================================================================
static const int SMEM_STG = 32768;              // Ah|Al|Bh|Bl, 8KB each
static const int SMEM_TOT = 3 * SMEM_STG;       // 96 KB

template <bool RESID, bool WN, bool WH, bool WHT>
__global__ __launch_bounds__(256, 1)
void gemm_mma(const __half* __restrict__ Ahg, const __half* __restrict__ Alg,
              const __half* __restrict__ Bhg, const __half* __restrict__ Blg,
              float* __restrict__ Cn,
              __half* __restrict__ CHh, __half* __restrict__ CHl,
              __half* __restrict__ CTh, __half* __restrict__ CTl,
              const float* __restrict__ Rg, const float* __restrict__ gamma,
              int K, int ldA, int ldB, int ldC, int ldT,
              long aBat, long bBat, long cBat, long tBat, int nsplit)
{
    extern __shared__ __align__(128) char sm[];
    const u32 smb = smem_u32(sm);
    const int tid = threadIdx.x;
    const int wid = tid >> 5;
    const int lid = tid & 31;
    const int wm  = wid >> 2;          // 0..1
    const int wn  = wid & 3;           // 0..3

    const int z = blockIdx.z;
    const int b = z / nsplit;
    const int s = z - b * nsplit;
    const int nbat = gridDim.z / nsplit;

    const __half* Ah = Ahg + (size_t)b * aBat + (size_t)s * K;
    const __half* Al = Alg + (size_t)b * aBat + (size_t)s * K;
    const __half* Bh = Bhg + (size_t)b * bBat + (size_t)s * K;
    const __half* Bl = Blg + (size_t)b * bBat + (size_t)s * K;

    const size_t ob = (size_t)s * nbat + b;
    float*  Cb  = WN  ? (Cn  + ob * cBat) : nullptr;
    __half* CHhb = WH ? (CHh + ob * cBat) : nullptr;
    __half* CHlb = WH ? (CHl + ob * cBat) : nullptr;
    __half* CThb = WHT ? (CTh + ob * tBat) : nullptr;
    __half* CTlb = WHT ? (CTl + ob * tBat) : nullptr;
    const float* R = RESID ? (Rg + (size_t)b * cBat) : nullptr;

    const int m0 = blockIdx.y * 128;
    const int n0 = blockIdx.x * 128;

    const __half* Ahm = Ah + (size_t)m0 * ldA;
    const __half* Alm = Al + (size_t)m0 * ldA;
    const __half* Bhn = Bh + (size_t)n0 * ldB;
    const __half* Bln = Bl + (size_t)n0 * ldB;

    // lane constants for ldmatrix addressing (XOR-swizzled 16B chunks)
    const int rAl = lid & 15;
    const int ksA = lid >> 4;                    // 0/1 -> k half within k16
    const int xA  = (rAl >> 1) & 3;
    const int rBl = ((lid >> 4) & 1) * 8 + (lid & 7);
    const int csB = (lid >> 3) & 1;
    const int xB  = (rBl >> 1) & 3;

    // stage loader: 8 cp.async/thread (Ah,Al,Bh,Bl tiles, 128 rows x 64B)
    auto ldStage = [&](int chunk, int stg) {
        const u32 sb = smb + stg * SMEM_STG;
        const int kt = chunk * 32;
        #pragma unroll
        for (int p = 0; p < 2; p++) {
            const int idx = tid + p * 256;
            const int r = idx >> 2;
            const int c = idx & 3;
            const u32 soff = r * 64 + ((c ^ ((r >> 1) & 3)) << 4);
            const size_t ga = (size_t)r * ldA + kt + c * 8;
            const size_t gb = (size_t)r * ldB + kt + c * 8;
            cp16(sb + soff,          Ahm + ga);
            cp16(sb + 8192 + soff,   Alm + ga);
            cp16(sb + 16384 + soff,  Bhn + gb);
            cp16(sb + 24576 + soff,  Bln + gb);
        }
    };

    const int nC = K >> 5;

    float acc[4][4][4];
    #pragma unroll
    for (int i = 0; i < 4; i++)
        #pragma unroll
        for (int j = 0; j < 4; j++)
            #pragma unroll
            for (int q = 0; q < 4; q++) acc[i][j][q] = 0.0f;

    ldStage(0, 0); cp_commit();
    ldStage(1, 1); cp_commit();

    for (int c = 0; c < nC; c++) {
        if (c + 1 < nC) cp_wait<1>(); else cp_wait<0>();
        __syncthreads();
        if (c + 2 < nC) { ldStage(c + 2, (c + 2) % 3); cp_commit(); }

        const u32 tb = smb + (c % 3) * SMEM_STG;
        #pragma unroll
        for (int s16 = 0; s16 < 2; s16++) {
            u32 ah[4][4], al[4][4], bh[8], bl[8];
            #pragma unroll
            for (int mt = 0; mt < 4; mt++) {
                const u32 ra = (u32)((wm * 64 + mt * 16 + rAl) * 64 +
                                     (((2 * s16 + ksA) ^ xA) << 4));
                LDMX4(ah[mt][0], ah[mt][1], ah[mt][2], ah[mt][3], tb + ra);
                LDMX4(al[mt][0], al[mt][1], al[mt][2], al[mt][3],
                      tb + 8192 + ra);
            }
            const u32 rb = (u32)((wn * 32 + rBl) * 64 +
                                 (((2 * s16 + csB) ^ xB) << 4));
            LDMX4(bh[0], bh[1], bh[2], bh[3], tb + 16384 + rb);
            LDMX4(bh[4], bh[5], bh[6], bh[7], tb + 16384 + rb + 1024);
            LDMX4(bl[0], bl[1], bl[2], bl[3], tb + 24576 + rb);
            LDMX4(bl[4], bl[5], bl[6], bl[7], tb + 24576 + rb + 1024);

            #pragma unroll
            for (int mt = 0; mt < 4; mt++)
                #pragma unroll
                for (int nt = 0; nt < 4; nt++) {
                    MMA16816(acc[mt][nt], ah[mt], bh[2*nt], bh[2*nt+1]);
                    MMA16816(acc[mt][nt], ah[mt], bl[2*nt], bl[2*nt+1]);
                    MMA16816(acc[mt][nt], al[mt], bh[2*nt], bh[2*nt+1]);
                }
        }
    }

    // ---------------- epilogue ----------------
    const float gm = RESID ? gamma[0] : 0.0f;
    #pragma unroll
    for (int mt = 0; mt < 4; mt++) {
        #pragma unroll
        for (int nt = 0; nt < 4; nt++) {
            const int nn = n0 + wn * 32 + nt * 8 + (lid & 3) * 2;
            #pragma unroll
            for (int h = 0; h < 2; h++) {
                const int mm = m0 + wm * 64 + mt * 16 + (lid >> 2) + h * 8;
                float v0 = acc[mt][nt][2 * h];
                float v1 = acc[mt][nt][2 * h + 1];
                if (RESID) {
                    const float2 rr = *(const float2*)(R + (size_t)mm * ldC + nn);
                    v0 = gm * v0 + rr.x;
                    v1 = gm * v1 + rr.y;
                }
                if (WN)
                    *(float2*)(Cb + (size_t)mm * ldC + nn) = make_float2(v0, v1);
                if (WH || WHT) {
                    const __half h0 = __float2half_rn(v0);
                    const __half h1 = __float2half_rn(v1);
                    const __half e0 = __float2half_rn(v0 - __half2float(h0));
                    const __half e1 = __float2half_rn(v1 - __half2float(h1));
                    if (WH) {
                        *(__half2*)(CHhb + (size_t)mm * ldC + nn) =
                            __halves2half2(h0, h1);
                        *(__half2*)(CHlb + (size_t)mm * ldC + nn) =
                            __halves2half2(e0, e1);
                    }
                    if (WHT) {
                        CThb[(size_t)nn * ldT + mm]       = h0;
                        CThb[(size_t)(nn + 1) * ldT + mm] = h1;
                        CTlb[(size_t)nn * ldT + mm]       = e0;
                        CTlb[(size_t)(nn + 1) * ldT + mm] = e1;
                    }
                }
            }
        }
    }
}

// ===========================================================================
// Transpose + fp16 hi/lo split: in fp32 [R,C] -> outH/outL fp16 [C,R] (batched)
// ===========================================================================
__global__ __launch_bounds__(256)
void transpose_split(const float* __restrict__ in, __half* __restrict__ oh,
                     __half* __restrict__ ol, int R, int C)
{
    __shared__ float t[32][33];
    const size_t bo = (size_t)blockIdx.z * R * C;
    const float* ip = in + bo;
    __half* oph = oh + bo;
    __half* opl = ol + bo;
    const int tx = threadIdx.x & 31;
    const int ty = threadIdx.x >> 5;
    const int x = blockIdx.x * 32 + tx;
    const int y = blockIdx.y * 32 + ty;
    #pragma unroll
    for (int j = 0; j < 32; j += 8)
        t[ty + j][tx] = ip[(size_t)(y + j) * C + x];
    __syncthreads();
    const int ox = blockIdx.y * 32 + tx;
    const int oy = blockIdx.x * 32 + ty;
    #pragma unroll
    for (int j = 0; j < 32; j += 8) {
        const float v = t[tx][ty + j];
        const __half hh = __float2half_rn(v);
        oph[(size_t)(oy + j) * R + ox] = hh;
        opl[(size_t)(oy + j) * R + ox] = __float2half_rn(v - __half2float(hh));
    }
}

// fp32 -> fp16 hi/lo split (weights)
__global__ __launch_bounds__(256)
void split_w(const float* __restrict__ in, __half* __restrict__ oh,
             __half* __restrict__ ol, int n)
{
    const int i = blockIdx.x * 256 + threadIdx.x;
    if (i < n) {
        const float v = in[i];
        const __half hh = __float2half_rn(v);
        oh[i] = hh;
        ol[i] = __float2half_rn(v - __half2float(hh));
    }
}

// ===========================================================================
// Softmax over rows of 256 (sums NSPLIT split-K partials), emits hi/lo fp16.
// ===========================================================================
__global__ __launch_bounds__(256)
void softmax_rows(const float* __restrict__ P, __half* __restrict__ Ah,
                  __half* __restrict__ Al)
{
    const size_t RS = (size_t)BATCH * CCH * CCH;
    const int row = blockIdx.x;
    const int tid = threadIdx.x;
    const size_t base = (size_t)row * CCH + tid;
    float x = 0.0f;
    #pragma unroll
    for (int s = 0; s < NSPLIT; s++) x += P[s * RS + base];

    __shared__ float red[256];
    red[tid] = x;
    __syncthreads();
    for (int o = 128; o > 0; o >>= 1) {
        if (tid < o) red[tid] = fmaxf(red[tid], red[tid + o]);
        __syncthreads();
    }
    const float mx = red[0];
    __syncthreads();
    const float e = expf(x - mx);
    red[tid] = e;
    __syncthreads();
    for (int o = 128; o > 0; o >>= 1) {
        if (tid < o) red[tid] += red[tid + o];
        __syncthreads();
    }
    const float p = e / red[0];
    const __half hh = __float2half_rn(p);
    Ah[base] = hh;
    Al[base] = __float2half_rn(p - __half2float(hh));
}

// ===========================================================================
// Launch
// ===========================================================================
extern "C" void kernel_launch(void* const* d_in, const int* in_sizes, int n_in,
                              void* d_out, int out_size)
{
    const float* x1    = (const float*)d_in[0];  // [16,512,64,64]
    const float* x2    = (const float*)d_in[1];  // [16,320,64,64]
    const float* w_img = (const float*)d_in[2];  // [256,512]
    const float* w_txt = (const float*)d_in[3];  // [256,320]
    const float* w_out = (const float*)d_in[4];  // [512,256]
    const float* gamma = (const float*)d_in[5];  // [1]
    float* out = (float*)d_out;                  // [16,512,64,64]

    __half *x1Th, *x1Tl, *x2Th, *x2Tl, *wih, *wil, *wth, *wtl, *woh, *wol;
    __half *imgh, *imgl, *kvh, *kvl, *kvTh, *kvTl, *tTh, *tTl, *atth, *attl;
    float *img, *part;
    cudaGetSymbolAddress((void**)&x1Th, g_x1Th);
    cudaGetSymbolAddress((void**)&x1Tl, g_x1Tl);
    cudaGetSymbolAddress((void**)&x2Th, g_x2Th);
    cudaGetSymbolAddress((void**)&x2Tl, g_x2Tl);
    cudaGetSymbolAddress((void**)&wih,  g_wih);
    cudaGetSymbolAddress((void**)&wil,  g_wil);
    cudaGetSymbolAddress((void**)&wth,  g_wth);
    cudaGetSymbolAddress((void**)&wtl,  g_wtl);
    cudaGetSymbolAddress((void**)&woh,  g_woh);
    cudaGetSymbolAddress((void**)&wol,  g_wol);
    cudaGetSymbolAddress((void**)&img,  g_img);
    cudaGetSymbolAddress((void**)&imgh, g_imgh);
    cudaGetSymbolAddress((void**)&imgl, g_imgl);
    cudaGetSymbolAddress((void**)&kvh,  g_kvh);
    cudaGetSymbolAddress((void**)&kvl,  g_kvl);
    cudaGetSymbolAddress((void**)&kvTh, g_kvTh);
    cudaGetSymbolAddress((void**)&kvTl, g_kvTl);
    cudaGetSymbolAddress((void**)&tTh,  g_tTh);
    cudaGetSymbolAddress((void**)&tTl,  g_tTl);
    cudaGetSymbolAddress((void**)&part, g_part);
    cudaGetSymbolAddress((void**)&atth, g_atth);
    cudaGetSymbolAddress((void**)&attl, g_attl);

    cudaFuncSetAttribute(gemm_mma<false, true,  true,  false>,
                         cudaFuncAttributeMaxDynamicSharedMemorySize, SMEM_TOT);
    cudaFuncSetAttribute(gemm_mma<false, false, true,  true >,
                         cudaFuncAttributeMaxDynamicSharedMemorySize, SMEM_TOT);
    cudaFuncSetAttribute(gemm_mma<false, true,  false, false>,
                         cudaFuncAttributeMaxDynamicSharedMemorySize, SMEM_TOT);
    cudaFuncSetAttribute(gemm_mma<true,  false, false, true >,
                         cudaFuncAttributeMaxDynamicSharedMemorySize, SMEM_TOT);

    // 0) operand prep: transposed + split activations, split weights
    transpose_split<<<dim3(128, 16, 16), 256>>>(x1, x1Th, x1Tl, 512, 4096);
    transpose_split<<<dim3(128, 10, 16), 256>>>(x2, x2Th, x2Tl, 320, 4096);
    split_w<<<512, 256>>>(w_img, wih, wil, 256 * 512);
    split_w<<<320, 256>>>(w_txt, wth, wtl, 256 * 320);
    split_w<<<512, 256>>>(w_out, woh, wol, 512 * 256);

    // 1) img[c,n] = sum_k w_img[c,k]*x1T[n,k]; write fp32 img + hi/lo split
    gemm_mma<false, true, true, false><<<dim3(32, 2, 16), 256, SMEM_TOT>>>(
        wih, wil, x1Th, x1Tl, img, imgh, imgl, nullptr, nullptr,
        nullptr, nullptr,
        512, 512, 512, 4096, 0,
        0L, 4096L * 512, 256L * 4096, 0L, 1);

    // 2) kv: write hi/lo [c,n] and transposed hi/lo [n,c]
    gemm_mma<false, false, true, true><<<dim3(32, 2, 16), 256, SMEM_TOT>>>(
        wth, wtl, x2Th, x2Tl, nullptr, kvh, kvl, kvTh, kvTl,
        nullptr, nullptr,
        320, 320, 320, 4096, 256,
        0L, 4096L * 320, 256L * 4096, 4096L * 256, 1);

    // 3) logits partials (split-K=8): part[s,b][c,d] = sum_n img[c,n]*kv[d,n]
    gemm_mma<false, true, false, false><<<dim3(2, 2, 16 * NSPLIT), 256, SMEM_TOT>>>(
        imgh, imgl, kvh, kvl, part, nullptr, nullptr, nullptr, nullptr,
        nullptr, nullptr,
        NSP / NSPLIT, 4096, 4096, 256, 0,
        256L * 4096, 256L * 4096, 256L * 256, 0L, NSPLIT);

    // 4) softmax (sums partials), emit attn hi/lo
    softmax_rows<<<BATCH * CCH, 256>>>(part, atth, attl);

    // 5) tT[n,c] = gamma*sum_d attn[c,d]*kvT[n,d] + img[c,n]; write hi/lo [n,c]
    gemm_mma<true, false, false, true><<<dim3(32, 2, 16), 256, SMEM_TOT>>>(
        atth, attl, kvTh, kvTl, nullptr, nullptr, nullptr, tTh, tTl,
        img, gamma,
        256, 256, 256, 4096, 256,
        256L * 256, 4096L * 256, 256L * 4096, 4096L * 256, 1);

    // 6) out[o,n] = sum_c w_out[o,c]*tT[n,c]
    gemm_mma<false, true, false, false><<<dim3(32, 4, 16), 256, SMEM_TOT>>>(
        woh, wol, tTh, tTl, out, nullptr, nullptr, nullptr, nullptr,
        nullptr, nullptr,
        256, 256, 256, 4096, 0,
        0L, 4096L * 256, 512L * 4096, 0L, 1);
}

// round 4
// speedup vs baseline: 2.5670x; 1.1271x over previous
#include <cuda_runtime.h>
#include <cuda_fp16.h>
#include <math.h>

using u32 = unsigned int;

// ===========================================================================
// Problem constants
// ===========================================================================
static const int BATCH  = 16;
static const int CCH    = 256;
static const int NSP    = 4096;
static const int NSPLIT = 8;     // split-K for logits GEMM

// ===========================================================================
// Device scratch (allocation-free). fp16 hi/lo split operand copies.
// ===========================================================================
__device__ __half g_x1Th[(size_t)BATCH * NSP * 512];
__device__ __half g_x1Tl[(size_t)BATCH * NSP * 512];
__device__ __half g_x2Th[(size_t)BATCH * NSP * 320];
__device__ __half g_x2Tl[(size_t)BATCH * NSP * 320];
__device__ __half g_wih[256 * 512], g_wil[256 * 512];
__device__ __half g_wth[256 * 320], g_wtl[256 * 320];
__device__ __half g_woh[512 * 256], g_wol[512 * 256];
__device__ float  g_img [(size_t)BATCH * CCH * NSP];
__device__ __half g_imgh[(size_t)BATCH * CCH * NSP];
__device__ __half g_imgl[(size_t)BATCH * CCH * NSP];
__device__ __half g_kvh [(size_t)BATCH * CCH * NSP];
__device__ __half g_kvl [(size_t)BATCH * CCH * NSP];
__device__ __half g_kvTh[(size_t)BATCH * NSP * CCH];
__device__ __half g_tTh [(size_t)BATCH * NSP * CCH];
__device__ float  g_part[(size_t)NSPLIT * BATCH * CCH * CCH];
__device__ __half g_atth[(size_t)BATCH * CCH * CCH];
__device__ __half g_attl[(size_t)BATCH * CCH * CCH];

// ===========================================================================
// PTX helpers (base-target ISA: cp.async / ldmatrix / mma.sync)
// ===========================================================================
__device__ __forceinline__ u32 smem_u32(const void* p) {
    u32 a;
    asm("{ .reg .u64 t; cvta.to.shared.u64 t, %1; cvt.u32.u64 %0, t; }"
        : "=r"(a) : "l"(p));
    return a;
}
__device__ __forceinline__ void cp16(u32 dst, const void* src) {
    asm volatile("cp.async.cg.shared.global [%0], [%1], 16;"
                 :: "r"(dst), "l"(src) : "memory");
}
__device__ __forceinline__ void cp_commit() {
    asm volatile("cp.async.commit_group;" ::: "memory");
}
template <int N>
__device__ __forceinline__ void cp_wait() {
    asm volatile("cp.async.wait_group %0;" :: "n"(N) : "memory");
}
#define LDMX4(d0, d1, d2, d3, addr) \
    asm volatile("ldmatrix.sync.aligned.m8n8.x4.shared.b16 {%0,%1,%2,%3},[%4];" \
                 : "=r"(d0), "=r"(d1), "=r"(d2), "=r"(d3) : "r"(addr))
#define MMA16816(c, a, b0, b1) \
    asm volatile("mma.sync.aligned.m16n8k16.row.col.f32.f16.f16.f32 " \
                 "{%0,%1,%2,%3},{%4,%5,%6,%7},{%8,%9},{%0,%1,%2,%3};" \
                 : "+f"((c)[0]), "+f"((c)[1]), "+f"((c)[2]), "+f"((c)[3]) \
                 : "r"((a)[0]), "r"((a)[1]), "r"((a)[2]), "r"((a)[3]), \
                   "r"(b0), "r"(b1))

// ===========================================================================
// Unified NT fp16-split GEMM with fp32 accumulate.
// D[m,n] = sum_k A[m,k]*B[n,k]; A,B pre-split hi/lo fp16, K-major.
// PB=true : 3-pass Markidis (AhBh + AhBl + AlBh)
// PB=false: 2-pass (AhBh + AlBh)  — B-lo never loaded (post-softmax stages)
// CTA tile 128x128, BK=32, 8 warps (2x4), warp tile 64x32, 3-stage cp.async.
// RESID: v = gamma*acc + R[m,n].
// WN: fp32 C[m,n].  WH: hi/lo fp16 at [m,n].  WHT: hi fp16 at [n,m].
// ===========================================================================
static const int SMEM_STG = 32768;              // Ah|Al|Bh|Bl, 8KB each
static const int SMEM_TOT = 3 * SMEM_STG;       // 96 KB

template <bool RESID, bool WN, bool WH, bool WHT, bool PB>
__global__ __launch_bounds__(256, 1)
void gemm_mma(const __half* __restrict__ Ahg, const __half* __restrict__ Alg,
              const __half* __restrict__ Bhg, const __half* __restrict__ Blg,
              float* __restrict__ Cn,
              __half* __restrict__ CHh, __half* __restrict__ CHl,
              __half* __restrict__ CTh,
              const float* __restrict__ Rg, const float* __restrict__ gamma,
              int K, int ldA, int ldB, int ldC, int ldT,
              long aBat, long bBat, long cBat, long tBat, int nsplit)
{
    extern __shared__ __align__(128) char sm[];
    const u32 smb = smem_u32(sm);
    const int tid = threadIdx.x;
    const int wid = tid >> 5;
    const int lid = tid & 31;
    const int wm  = wid >> 2;          // 0..1
    const int wn  = wid & 3;           // 0..3

    const int z = blockIdx.z;
    const int b = z / nsplit;
    const int s = z - b * nsplit;
    const int nbat = gridDim.z / nsplit;

    const __half* Ah = Ahg + (size_t)b * aBat + (size_t)s * K;
    const __half* Al = Alg + (size_t)b * aBat + (size_t)s * K;
    const __half* Bh = Bhg + (size_t)b * bBat + (size_t)s * K;
    const __half* Bl = PB ? (Blg + (size_t)b * bBat + (size_t)s * K) : nullptr;

    const size_t ob = (size_t)s * nbat + b;
    float*  Cb   = WN  ? (Cn  + ob * cBat) : nullptr;
    __half* CHhb = WH  ? (CHh + ob * cBat) : nullptr;
    __half* CHlb = WH  ? (CHl + ob * cBat) : nullptr;
    __half* CThb = WHT ? (CTh + ob * tBat) : nullptr;
    const float* R = RESID ? (Rg + (size_t)b * cBat) : nullptr;

    const int m0 = blockIdx.y * 128;
    const int n0 = blockIdx.x * 128;

    const __half* Ahm = Ah + (size_t)m0 * ldA;
    const __half* Alm = Al + (size_t)m0 * ldA;
    const __half* Bhn = Bh + (size_t)n0 * ldB;
    const __half* Bln = PB ? (Bl + (size_t)n0 * ldB) : nullptr;

    // lane constants for ldmatrix addressing (XOR-swizzled 16B chunks)
    const int rAl = lid & 15;
    const int ksA = lid >> 4;
    const int xA  = (rAl >> 1) & 3;
    const int rBl = ((lid >> 4) & 1) * 8 + (lid & 7);
    const int csB = (lid >> 3) & 1;
    const int xB  = (rBl >> 1) & 3;

    auto ldStage = [&](int chunk, int stg) {
        const u32 sb = smb + stg * SMEM_STG;
        const int kt = chunk * 32;
        #pragma unroll
        for (int p = 0; p < 2; p++) {
            const int idx = tid + p * 256;
            const int r = idx >> 2;
            const int c = idx & 3;
            const u32 soff = r * 64 + ((c ^ ((r >> 1) & 3)) << 4);
            const size_t ga = (size_t)r * ldA + kt + c * 8;
            const size_t gb = (size_t)r * ldB + kt + c * 8;
            cp16(sb + soff,          Ahm + ga);
            cp16(sb + 8192 + soff,   Alm + ga);
            cp16(sb + 16384 + soff,  Bhn + gb);
            if constexpr (PB) cp16(sb + 24576 + soff, Bln + gb);
        }
    };

    const int nC = K >> 5;

    float acc[4][4][4];
    #pragma unroll
    for (int i = 0; i < 4; i++)
        #pragma unroll
        for (int j = 0; j < 4; j++)
            #pragma unroll
            for (int q = 0; q < 4; q++) acc[i][j][q] = 0.0f;

    ldStage(0, 0); cp_commit();
    ldStage(1, 1); cp_commit();

    for (int c = 0; c < nC; c++) {
        if (c + 1 < nC) cp_wait<1>(); else cp_wait<0>();
        __syncthreads();
        if (c + 2 < nC) { ldStage(c + 2, (c + 2) % 3); cp_commit(); }

        const u32 tb = smb + (c % 3) * SMEM_STG;
        #pragma unroll
        for (int s16 = 0; s16 < 2; s16++) {
            u32 ah[4][4], al[4][4], bh[8], bl[8];
            #pragma unroll
            for (int mt = 0; mt < 4; mt++) {
                const u32 ra = (u32)((wm * 64 + mt * 16 + rAl) * 64 +
                                     (((2 * s16 + ksA) ^ xA) << 4));
                LDMX4(ah[mt][0], ah[mt][1], ah[mt][2], ah[mt][3], tb + ra);
                LDMX4(al[mt][0], al[mt][1], al[mt][2], al[mt][3],
                      tb + 8192 + ra);
            }
            const u32 rb = (u32)((wn * 32 + rBl) * 64 +
                                 (((2 * s16 + csB) ^ xB) << 4));
            LDMX4(bh[0], bh[1], bh[2], bh[3], tb + 16384 + rb);
            LDMX4(bh[4], bh[5], bh[6], bh[7], tb + 16384 + rb + 1024);
            if constexpr (PB) {
                LDMX4(bl[0], bl[1], bl[2], bl[3], tb + 24576 + rb);
                LDMX4(bl[4], bl[5], bl[6], bl[7], tb + 24576 + rb + 1024);
            }

            #pragma unroll
            for (int mt = 0; mt < 4; mt++)
                #pragma unroll
                for (int nt = 0; nt < 4; nt++) {
                    MMA16816(acc[mt][nt], ah[mt], bh[2*nt], bh[2*nt+1]);
                    if constexpr (PB)
                        MMA16816(acc[mt][nt], ah[mt], bl[2*nt], bl[2*nt+1]);
                    MMA16816(acc[mt][nt], al[mt], bh[2*nt], bh[2*nt+1]);
                }
        }
    }

    // ---------------- epilogue ----------------
    const float gm = RESID ? gamma[0] : 0.0f;
    #pragma unroll
    for (int mt = 0; mt < 4; mt++) {
        #pragma unroll
        for (int nt = 0; nt < 4; nt++) {
            const int nn = n0 + wn * 32 + nt * 8 + (lid & 3) * 2;
            #pragma unroll
            for (int h = 0; h < 2; h++) {
                const int mm = m0 + wm * 64 + mt * 16 + (lid >> 2) + h * 8;
                float v0 = acc[mt][nt][2 * h];
                float v1 = acc[mt][nt][2 * h + 1];
                if (RESID) {
                    const float2 rr = *(const float2*)(R + (size_t)mm * ldC + nn);
                    v0 = gm * v0 + rr.x;
                    v1 = gm * v1 + rr.y;
                }
                if (WN)
                    *(float2*)(Cb + (size_t)mm * ldC + nn) = make_float2(v0, v1);
                if (WH || WHT) {
                    const __half h0 = __float2half_rn(v0);
                    const __half h1 = __float2half_rn(v1);
                    if (WH) {
                        const __half e0 = __float2half_rn(v0 - __half2float(h0));
                        const __half e1 = __float2half_rn(v1 - __half2float(h1));
                        *(__half2*)(CHhb + (size_t)mm * ldC + nn) =
                            __halves2half2(h0, h1);
                        *(__half2*)(CHlb + (size_t)mm * ldC + nn) =
                            __halves2half2(e0, e1);
                    }
                    if (WHT) {
                        CThb[(size_t)nn * ldT + mm]       = h0;
                        CThb[(size_t)(nn + 1) * ldT + mm] = h1;
                    }
                }
            }
        }
    }
}

// ===========================================================================
// Transpose + fp16 hi/lo split: fp32 [R,C] -> fp16 [C,R] hi/lo (batched)
// ===========================================================================
__global__ __launch_bounds__(256)
void transpose_split(const float* __restrict__ in, __half* __restrict__ oh,
                     __half* __restrict__ ol, int R, int C)
{
    __shared__ float t[32][33];
    const size_t bo = (size_t)blockIdx.z * R * C;
    const float* ip = in + bo;
    __half* oph = oh + bo;
    __half* opl = ol + bo;
    const int tx = threadIdx.x & 31;
    const int ty = threadIdx.x >> 5;
    const int x = blockIdx.x * 32 + tx;
    const int y = blockIdx.y * 32 + ty;
    #pragma unroll
    for (int j = 0; j < 32; j += 8)
        t[ty + j][tx] = ip[(size_t)(y + j) * C + x];
    __syncthreads();
    const int ox = blockIdx.y * 32 + tx;
    const int oy = blockIdx.x * 32 + ty;
    #pragma unroll
    for (int j = 0; j < 32; j += 8) {
        const float v = t[tx][ty + j];
        const __half hh = __float2half_rn(v);
        oph[(size_t)(oy + j) * R + ox] = hh;
        opl[(size_t)(oy + j) * R + ox] = __float2half_rn(v - __half2float(hh));
    }
}

// fp32 -> fp16 hi/lo split (weights)
__global__ __launch_bounds__(256)
void split_w(const float* __restrict__ in, __half* __restrict__ oh,
             __half* __restrict__ ol, int n)
{
    const int i = blockIdx.x * 256 + threadIdx.x;
    if (i < n) {
        const float v = in[i];
        const __half hh = __float2half_rn(v);
        oh[i] = hh;
        ol[i] = __float2half_rn(v - __half2float(hh));
    }
}

// ===========================================================================
// Softmax over rows of 256 (sums NSPLIT split-K partials), emits hi/lo fp16.
// ===========================================================================
__global__ __launch_bounds__(256)
void softmax_rows(const float* __restrict__ P, __half* __restrict__ Ah,
                  __half* __restrict__ Al)
{
    const size_t RS = (size_t)BATCH * CCH * CCH;
    const int row = blockIdx.x;
    const int tid = threadIdx.x;
    const size_t base = (size_t)row * CCH + tid;
    float x = 0.0f;
    #pragma unroll
    for (int s = 0; s < NSPLIT; s++) x += P[s * RS + base];

    __shared__ float red[256];
    red[tid] = x;
    __syncthreads();
    for (int o = 128; o > 0; o >>= 1) {
        if (tid < o) red[tid] = fmaxf(red[tid], red[tid + o]);
        __syncthreads();
    }
    const float mx = red[0];
    __syncthreads();
    const float e = expf(x - mx);
    red[tid] = e;
    __syncthreads();
    for (int o = 128; o > 0; o >>= 1) {
        if (tid < o) red[tid] += red[tid + o];
        __syncthreads();
    }
    const float p = e / red[0];
    const __half hh = __float2half_rn(p);
    Ah[base] = hh;
    Al[base] = __float2half_rn(p - __half2float(hh));
}

// ===========================================================================
// Launch
// ===========================================================================
extern "C" void kernel_launch(void* const* d_in, const int* in_sizes, int n_in,
                              void* d_out, int out_size)
{
    const float* x1    = (const float*)d_in[0];
    const float* x2    = (const float*)d_in[1];
    const float* w_img = (const float*)d_in[2];
    const float* w_txt = (const float*)d_in[3];
    const float* w_out = (const float*)d_in[4];
    const float* gamma = (const float*)d_in[5];
    float* out = (float*)d_out;

    __half *x1Th, *x1Tl, *x2Th, *x2Tl, *wih, *wil, *wth, *wtl, *woh, *wol;
    __half *imgh, *imgl, *kvh, *kvl, *kvTh, *tTh, *atth, *attl;
    float *img, *part;
    cudaGetSymbolAddress((void**)&x1Th, g_x1Th);
    cudaGetSymbolAddress((void**)&x1Tl, g_x1Tl);
    cudaGetSymbolAddress((void**)&x2Th, g_x2Th);
    cudaGetSymbolAddress((void**)&x2Tl, g_x2Tl);
    cudaGetSymbolAddress((void**)&wih,  g_wih);
    cudaGetSymbolAddress((void**)&wil,  g_wil);
    cudaGetSymbolAddress((void**)&wth,  g_wth);
    cudaGetSymbolAddress((void**)&wtl,  g_wtl);
    cudaGetSymbolAddress((void**)&woh,  g_woh);
    cudaGetSymbolAddress((void**)&wol,  g_wol);
    cudaGetSymbolAddress((void**)&img,  g_img);
    cudaGetSymbolAddress((void**)&imgh, g_imgh);
    cudaGetSymbolAddress((void**)&imgl, g_imgl);
    cudaGetSymbolAddress((void**)&kvh,  g_kvh);
    cudaGetSymbolAddress((void**)&kvl,  g_kvl);
    cudaGetSymbolAddress((void**)&kvTh, g_kvTh);
    cudaGetSymbolAddress((void**)&tTh,  g_tTh);
    cudaGetSymbolAddress((void**)&part, g_part);
    cudaGetSymbolAddress((void**)&atth, g_atth);
    cudaGetSymbolAddress((void**)&attl, g_attl);

    cudaFuncSetAttribute(gemm_mma<false, true,  true,  false, true >,
                         cudaFuncAttributeMaxDynamicSharedMemorySize, SMEM_TOT);
    cudaFuncSetAttribute(gemm_mma<false, false, true,  true,  true >,
                         cudaFuncAttributeMaxDynamicSharedMemorySize, SMEM_TOT);
    cudaFuncSetAttribute(gemm_mma<false, true,  false, false, true >,
                         cudaFuncAttributeMaxDynamicSharedMemorySize, SMEM_TOT);
    cudaFuncSetAttribute(gemm_mma<true,  false, false, true,  false>,
                         cudaFuncAttributeMaxDynamicSharedMemorySize, SMEM_TOT);
    cudaFuncSetAttribute(gemm_mma<false, true,  false, false, false>,
                         cudaFuncAttributeMaxDynamicSharedMemorySize, SMEM_TOT);

    // prep (interleaved with GEMMs so early ncu launch indices hit GEMMs)
    transpose_split<<<dim3(128, 16, 16), 256>>>(x1, x1Th, x1Tl, 512, 4096);  //0
    transpose_split<<<dim3(128, 10, 16), 256>>>(x2, x2Th, x2Tl, 320, 4096);  //1
    split_w<<<512, 256>>>(w_img, wih, wil, 256 * 512);                       //2

    // 1) img = w_img @ x1T  (3-pass); fp32 img + hi/lo split                //3
    gemm_mma<false, true, true, false, true><<<dim3(32, 2, 16), 256, SMEM_TOT>>>(
        wih, wil, x1Th, x1Tl, img, imgh, imgl, nullptr, nullptr, nullptr,
        512, 512, 512, 4096, 0, 0L, 4096L * 512, 256L * 4096, 0L, 1);

    split_w<<<320, 256>>>(w_txt, wth, wtl, 256 * 320);                       //4

    // 2) kv (3-pass): hi/lo [c,n] + transposed hi [n,c]                     //5
    gemm_mma<false, false, true, true, true><<<dim3(32, 2, 16), 256, SMEM_TOT>>>(
        wth, wtl, x2Th, x2Tl, nullptr, kvh, kvl, kvTh, nullptr, nullptr,
        320, 320, 320, 4096, 256, 0L, 4096L * 320, 256L * 4096, 4096L * 256, 1);

    split_w<<<512, 256>>>(w_out, woh, wol, 512 * 256);                       //6

    // 3) logits partials (3-pass, split-K=8)                                //7
    gemm_mma<false, true, false, false, true><<<dim3(2, 2, 16 * NSPLIT), 256, SMEM_TOT>>>(
        imgh, imgl, kvh, kvl, part, nullptr, nullptr, nullptr, nullptr, nullptr,
        NSP / NSPLIT, 4096, 4096, 256, 0,
        256L * 4096, 256L * 4096, 256L * 256, 0L, NSPLIT);

    // 4) softmax                                                            //8
    softmax_rows<<<BATCH * CCH, 256>>>(part, atth, attl);

    // 5) tT[n,c] = gamma*(attn @ kvT) + img  (2-pass, B-lo dropped)         //9
    gemm_mma<true, false, false, true, false><<<dim3(32, 2, 16), 256, SMEM_TOT>>>(
        atth, attl, kvTh, nullptr, nullptr, nullptr, nullptr, tTh, img, gamma,
        256, 256, 256, 4096, 256,
        256L * 256, 4096L * 256, 256L * 4096, 4096L * 256, 1);

    // 6) out = w_out @ tT  (2-pass, B-lo dropped)                           //10
    gemm_mma<false, true, false, false, false><<<dim3(32, 4, 16), 256, SMEM_TOT>>>(
        woh, wol, tTh, nullptr, out, nullptr, nullptr, nullptr, nullptr, nullptr,
        256, 256, 256, 4096, 0,
        0L, 4096L * 256, 512L * 4096, 0L, 1);
}

// round 5
// speedup vs baseline: 3.0673x; 1.1949x over previous
#include <cuda_runtime.h>
#include <cuda_fp16.h>
#include <math.h>

using u32 = unsigned int;

// ===========================================================================
// Problem constants
// ===========================================================================
static const int BATCH  = 16;
static const int CCH    = 256;
static const int NSP    = 4096;
static const int NSPLIT = 8;     // split-K for logits GEMM

// ===========================================================================
// Device scratch (allocation-free). fp16 hi/lo split operand copies.
// ===========================================================================
__device__ __half g_x1Th[(size_t)BATCH * NSP * 512];
__device__ __half g_x1Tl[(size_t)BATCH * NSP * 512];
__device__ __half g_x2Th[(size_t)BATCH * NSP * 320];
__device__ __half g_x2Tl[(size_t)BATCH * NSP * 320];
__device__ __half g_wih[256 * 512], g_wil[256 * 512];
__device__ __half g_wth[256 * 320], g_wtl[256 * 320];
__device__ __half g_woh[512 * 256], g_wol[512 * 256];
__device__ float  g_img [(size_t)BATCH * CCH * NSP];
__device__ __half g_imgh[(size_t)BATCH * CCH * NSP];
__device__ __half g_imgl[(size_t)BATCH * CCH * NSP];
__device__ __half g_kvh [(size_t)BATCH * CCH * NSP];
__device__ __half g_kvl [(size_t)BATCH * CCH * NSP];
__device__ __half g_kvTh[(size_t)BATCH * NSP * CCH];
__device__ __half g_tTh [(size_t)BATCH * NSP * CCH];
__device__ float  g_part[(size_t)NSPLIT * BATCH * CCH * CCH];
__device__ __half g_atth[(size_t)BATCH * CCH * CCH];
__device__ __half g_attl[(size_t)BATCH * CCH * CCH];

// ===========================================================================
// PTX helpers (base-target ISA: cp.async / ldmatrix / mma.sync)
// ===========================================================================
__device__ __forceinline__ u32 smem_u32(const void* p) {
    u32 a;
    asm("{ .reg .u64 t; cvta.to.shared.u64 t, %1; cvt.u32.u64 %0, t; }"
        : "=r"(a) : "l"(p));
    return a;
}
__device__ __forceinline__ void cp16(u32 dst, const void* src) {
    asm volatile("cp.async.cg.shared.global [%0], [%1], 16;"
                 :: "r"(dst), "l"(src) : "memory");
}
__device__ __forceinline__ void cp_commit() {
    asm volatile("cp.async.commit_group;" ::: "memory");
}
template <int N>
__device__ __forceinline__ void cp_wait() {
    asm volatile("cp.async.wait_group %0;" :: "n"(N) : "memory");
}
#define LDMX4(d0, d1, d2, d3, addr) \
    asm volatile("ldmatrix.sync.aligned.m8n8.x4.shared.b16 {%0,%1,%2,%3},[%4];" \
                 : "=r"(d0), "=r"(d1), "=r"(d2), "=r"(d3) : "r"(addr))
#define MMA16816(c, a, b0, b1) \
    asm volatile("mma.sync.aligned.m16n8k16.row.col.f32.f16.f16.f32 " \
                 "{%0,%1,%2,%3},{%4,%5,%6,%7},{%8,%9},{%0,%1,%2,%3};" \
                 : "+f"((c)[0]), "+f"((c)[1]), "+f"((c)[2]), "+f"((c)[3]) \
                 : "r"((a)[0]), "r"((a)[1]), "r"((a)[2]), "r"((a)[3]), \
                   "r"(b0), "r"(b1))

// ===========================================================================
// Unified NT fp16-split GEMM with fp32 accumulate.
// D[m,n] = sum_k A[m,k]*B[n,k]; A,B pre-split hi/lo fp16, K-major.
// PB=true : 3-pass Markidis (AhBh + AhBl + AlBh)
// PB=false: 2-pass (AhBh + AlBh)
// CTA tile 128x128, BK=32, 8 warps (2x4), 3-stage cp.async, 2 CTAs/SM.
// RESID: v = gamma*acc + R[m,n].
// WN: fp32 C[m,n].  WH: hi/lo fp16 [m,n].  WHT: hi fp16 [n,m] via smem-staged
// transpose (coalesced 16B stores).
// ===========================================================================
static const int SMEM_STG = 32768;              // Ah|Al|Bh|Bl, 8KB each
static const int SMEM_TOT = 3 * SMEM_STG;       // 96 KB

template <bool RESID, bool WN, bool WH, bool WHT, bool PB>
__global__ __launch_bounds__(256, 2)
void gemm_mma(const __half* __restrict__ Ahg, const __half* __restrict__ Alg,
              const __half* __restrict__ Bhg, const __half* __restrict__ Blg,
              float* __restrict__ Cn,
              __half* __restrict__ CHh, __half* __restrict__ CHl,
              __half* __restrict__ CTh,
              const float* __restrict__ Rg, const float* __restrict__ gamma,
              int K, int ldA, int ldB, int ldC, int ldT,
              long aBat, long bBat, long cBat, long tBat, int nsplit)
{
    extern __shared__ __align__(128) char sm[];
    const u32 smb = smem_u32(sm);
    const int tid = threadIdx.x;
    const int wid = tid >> 5;
    const int lid = tid & 31;
    const int wm  = wid >> 2;          // 0..1
    const int wn  = wid & 3;           // 0..3

    const int z = blockIdx.z;
    const int b = z / nsplit;
    const int s = z - b * nsplit;
    const int nbat = gridDim.z / nsplit;

    const __half* Ah = Ahg + (size_t)b * aBat + (size_t)s * K;
    const __half* Al = Alg + (size_t)b * aBat + (size_t)s * K;
    const __half* Bh = Bhg + (size_t)b * bBat + (size_t)s * K;
    const __half* Bl = PB ? (Blg + (size_t)b * bBat + (size_t)s * K) : nullptr;

    const size_t ob = (size_t)s * nbat + b;
    float*  Cb   = WN  ? (Cn  + ob * cBat) : nullptr;
    __half* CHhb = WH  ? (CHh + ob * cBat) : nullptr;
    __half* CHlb = WH  ? (CHl + ob * cBat) : nullptr;
    __half* CThb = WHT ? (CTh + ob * tBat) : nullptr;
    const float* R = RESID ? (Rg + (size_t)b * cBat) : nullptr;

    const int m0 = blockIdx.y * 128;
    const int n0 = blockIdx.x * 128;

    const __half* Ahm = Ah + (size_t)m0 * ldA;
    const __half* Alm = Al + (size_t)m0 * ldA;
    const __half* Bhn = Bh + (size_t)n0 * ldB;
    const __half* Bln = PB ? (Bl + (size_t)n0 * ldB) : nullptr;

    // lane constants for ldmatrix addressing (XOR-swizzled 16B chunks)
    const int rAl = lid & 15;
    const int ksA = lid >> 4;
    const int xA  = (rAl >> 1) & 3;
    const int rBl = ((lid >> 4) & 1) * 8 + (lid & 7);
    const int csB = (lid >> 3) & 1;
    const int xB  = (rBl >> 1) & 3;

    auto ldStage = [&](int chunk, int stg) {
        const u32 sb = smb + stg * SMEM_STG;
        const int kt = chunk * 32;
        #pragma unroll
        for (int p = 0; p < 2; p++) {
            const int idx = tid + p * 256;
            const int r = idx >> 2;
            const int c = idx & 3;
            const u32 soff = r * 64 + ((c ^ ((r >> 1) & 3)) << 4);
            const size_t ga = (size_t)r * ldA + kt + c * 8;
            const size_t gb = (size_t)r * ldB + kt + c * 8;
            cp16(sb + soff,          Ahm + ga);
            cp16(sb + 8192 + soff,   Alm + ga);
            cp16(sb + 16384 + soff,  Bhn + gb);
            if constexpr (PB) cp16(sb + 24576 + soff, Bln + gb);
        }
    };

    const int nC = K >> 5;

    float acc[4][4][4];
    #pragma unroll
    for (int i = 0; i < 4; i++)
        #pragma unroll
        for (int j = 0; j < 4; j++)
            #pragma unroll
            for (int q = 0; q < 4; q++) acc[i][j][q] = 0.0f;

    ldStage(0, 0); cp_commit();
    ldStage(1, 1); cp_commit();

    for (int c = 0; c < nC; c++) {
        if (c + 1 < nC) cp_wait<1>(); else cp_wait<0>();
        __syncthreads();
        if (c + 2 < nC) { ldStage(c + 2, (c + 2) % 3); cp_commit(); }

        const u32 tb = smb + (c % 3) * SMEM_STG;
        #pragma unroll
        for (int s16 = 0; s16 < 2; s16++) {
            u32 bh[8], bl[8];
            const u32 rb = (u32)((wn * 32 + rBl) * 64 +
                                 (((2 * s16 + csB) ^ xB) << 4));
            LDMX4(bh[0], bh[1], bh[2], bh[3], tb + 16384 + rb);
            LDMX4(bh[4], bh[5], bh[6], bh[7], tb + 16384 + rb + 1024);
            if constexpr (PB) {
                LDMX4(bl[0], bl[1], bl[2], bl[3], tb + 24576 + rb);
                LDMX4(bl[4], bl[5], bl[6], bl[7], tb + 24576 + rb + 1024);
            }
            #pragma unroll
            for (int mt = 0; mt < 4; mt++) {
                u32 ah[4], al[4];
                const u32 ra = (u32)((wm * 64 + mt * 16 + rAl) * 64 +
                                     (((2 * s16 + ksA) ^ xA) << 4));
                LDMX4(ah[0], ah[1], ah[2], ah[3], tb + ra);
                LDMX4(al[0], al[1], al[2], al[3], tb + 8192 + ra);
                #pragma unroll
                for (int nt = 0; nt < 4; nt++) {
                    MMA16816(acc[mt][nt], ah, bh[2*nt], bh[2*nt+1]);
                    if constexpr (PB)
                        MMA16816(acc[mt][nt], ah, bl[2*nt], bl[2*nt+1]);
                    MMA16816(acc[mt][nt], al, bh[2*nt], bh[2*nt+1]);
                }
            }
        }
    }

    // ---------------- epilogue ----------------
    if (WHT) __syncthreads();   // smem stages now reusable as transpose buffer
    __half* T = (__half*)sm;    // [128 n][136 m-halves] padded (bank-safe)

    const float gm = RESID ? gamma[0] : 0.0f;
    #pragma unroll
    for (int mt = 0; mt < 4; mt++) {
        #pragma unroll
        for (int nt = 0; nt < 4; nt++) {
            const int nn = wn * 32 + nt * 8 + (lid & 3) * 2;
            #pragma unroll
            for (int h = 0; h < 2; h++) {
                const int ml = wm * 64 + mt * 16 + (lid >> 2) + h * 8;
                const int mm = m0 + ml;
                float v0 = acc[mt][nt][2 * h];
                float v1 = acc[mt][nt][2 * h + 1];
                if (RESID) {
                    const float2 rr =
                        *(const float2*)(R + (size_t)mm * ldC + n0 + nn);
                    v0 = gm * v0 + rr.x;
                    v1 = gm * v1 + rr.y;
                }
                if (WN)
                    *(float2*)(Cb + (size_t)mm * ldC + n0 + nn) =
                        make_float2(v0, v1);
                if (WH || WHT) {
                    const __half h0 = __float2half_rn(v0);
                    const __half h1 = __float2half_rn(v1);
                    if (WH) {
                        const __half e0 = __float2half_rn(v0 - __half2float(h0));
                        const __half e1 = __float2half_rn(v1 - __half2float(h1));
                        *(__half2*)(CHhb + (size_t)mm * ldC + n0 + nn) =
                            __halves2half2(h0, h1);
                        *(__half2*)(CHlb + (size_t)mm * ldC + n0 + nn) =
                            __halves2half2(e0, e1);
                    }
                    if (WHT) {
                        T[(size_t)nn * 136 + ml]       = h0;
                        T[(size_t)(nn + 1) * 136 + ml] = h1;
                    }
                }
            }
        }
    }

    if (WHT) {
        __syncthreads();
        // coalesced copy-out: 128 n-rows x 16 chunks of 16B
        #pragma unroll
        for (int it = 0; it < 8; it++) {
            const int idx = it * 256 + tid;
            const int n  = idx >> 4;
            const int ck = idx & 15;
            const uint4 v = *(const uint4*)(T + (size_t)n * 136 + ck * 8);
            *(uint4*)(CThb + (size_t)(n0 + n) * ldT + m0 + ck * 8) = v;
        }
    }
}

// ===========================================================================
// Transpose + fp16 hi/lo split: fp32 [R,C] -> fp16 [C,R] hi/lo (batched)
// ===========================================================================
__global__ __launch_bounds__(256)
void transpose_split(const float* __restrict__ in, __half* __restrict__ oh,
                     __half* __restrict__ ol, int R, int C)
{
    __shared__ float t[32][33];
    const size_t bo = (size_t)blockIdx.z * R * C;
    const float* ip = in + bo;
    __half* oph = oh + bo;
    __half* opl = ol + bo;
    const int tx = threadIdx.x & 31;
    const int ty = threadIdx.x >> 5;
    const int x = blockIdx.x * 32 + tx;
    const int y = blockIdx.y * 32 + ty;
    #pragma unroll
    for (int j = 0; j < 32; j += 8)
        t[ty + j][tx] = ip[(size_t)(y + j) * C + x];
    __syncthreads();
    const int ox = blockIdx.y * 32 + tx;
    const int oy = blockIdx.x * 32 + ty;
    #pragma unroll
    for (int j = 0; j < 32; j += 8) {
        const float v = t[tx][ty + j];
        const __half hh = __float2half_rn(v);
        oph[(size_t)(oy + j) * R + ox] = hh;
        opl[(size_t)(oy + j) * R + ox] = __float2half_rn(v - __half2float(hh));
    }
}

// fp32 -> fp16 hi/lo split (weights)
__global__ __launch_bounds__(256)
void split_w(const float* __restrict__ in, __half* __restrict__ oh,
             __half* __restrict__ ol, int n)
{
    const int i = blockIdx.x * 256 + threadIdx.x;
    if (i < n) {
        const float v = in[i];
        const __half hh = __float2half_rn(v);
        oh[i] = hh;
        ol[i] = __float2half_rn(v - __half2float(hh));
    }
}

// ===========================================================================
// Softmax over rows of 256 (sums NSPLIT split-K partials), emits hi/lo fp16.
// ===========================================================================
__global__ __launch_bounds__(256)
void softmax_rows(const float* __restrict__ P, __half* __restrict__ Ah,
                  __half* __restrict__ Al)
{
    const size_t RS = (size_t)BATCH * CCH * CCH;
    const int row = blockIdx.x;
    const int tid = threadIdx.x;
    const size_t base = (size_t)row * CCH + tid;
    float x = 0.0f;
    #pragma unroll
    for (int s = 0; s < NSPLIT; s++) x += P[s * RS + base];

    __shared__ float red[256];
    red[tid] = x;
    __syncthreads();
    for (int o = 128; o > 0; o >>= 1) {
        if (tid < o) red[tid] = fmaxf(red[tid], red[tid + o]);
        __syncthreads();
    }
    const float mx = red[0];
    __syncthreads();
    const float e = expf(x - mx);
    red[tid] = e;
    __syncthreads();
    for (int o = 128; o > 0; o >>= 1) {
        if (tid < o) red[tid] += red[tid + o];
        __syncthreads();
    }
    const float p = e / red[0];
    const __half hh = __float2half_rn(p);
    Ah[base] = hh;
    Al[base] = __float2half_rn(p - __half2float(hh));
}

// ===========================================================================
// Launch
// ===========================================================================
extern "C" void kernel_launch(void* const* d_in, const int* in_sizes, int n_in,
                              void* d_out, int out_size)
{
    const float* x1    = (const float*)d_in[0];
    const float* x2    = (const float*)d_in[1];
    const float* w_img = (const float*)d_in[2];
    const float* w_txt = (const float*)d_in[3];
    const float* w_out = (const float*)d_in[4];
    const float* gamma = (const float*)d_in[5];
    float* out = (float*)d_out;

    __half *x1Th, *x1Tl, *x2Th, *x2Tl, *wih, *wil, *wth, *wtl, *woh, *wol;
    __half *imgh, *imgl, *kvh, *kvl, *kvTh, *tTh, *atth, *attl;
    float *img, *part;
    cudaGetSymbolAddress((void**)&x1Th, g_x1Th);
    cudaGetSymbolAddress((void**)&x1Tl, g_x1Tl);
    cudaGetSymbolAddress((void**)&x2Th, g_x2Th);
    cudaGetSymbolAddress((void**)&x2Tl, g_x2Tl);
    cudaGetSymbolAddress((void**)&wih,  g_wih);
    cudaGetSymbolAddress((void**)&wil,  g_wil);
    cudaGetSymbolAddress((void**)&wth,  g_wth);
    cudaGetSymbolAddress((void**)&wtl,  g_wtl);
    cudaGetSymbolAddress((void**)&woh,  g_woh);
    cudaGetSymbolAddress((void**)&wol,  g_wol);
    cudaGetSymbolAddress((void**)&img,  g_img);
    cudaGetSymbolAddress((void**)&imgh, g_imgh);
    cudaGetSymbolAddress((void**)&imgl, g_imgl);
    cudaGetSymbolAddress((void**)&kvh,  g_kvh);
    cudaGetSymbolAddress((void**)&kvl,  g_kvl);
    cudaGetSymbolAddress((void**)&kvTh, g_kvTh);
    cudaGetSymbolAddress((void**)&tTh,  g_tTh);
    cudaGetSymbolAddress((void**)&part, g_part);
    cudaGetSymbolAddress((void**)&atth, g_atth);
    cudaGetSymbolAddress((void**)&attl, g_attl);

    cudaFuncSetAttribute(gemm_mma<false, true,  true,  false, true >,
                         cudaFuncAttributeMaxDynamicSharedMemorySize, SMEM_TOT);
    cudaFuncSetAttribute(gemm_mma<false, false, true,  true,  true >,
                         cudaFuncAttributeMaxDynamicSharedMemorySize, SMEM_TOT);
    cudaFuncSetAttribute(gemm_mma<false, true,  false, false, true >,
                         cudaFuncAttributeMaxDynamicSharedMemorySize, SMEM_TOT);
    cudaFuncSetAttribute(gemm_mma<true,  false, false, true,  false>,
                         cudaFuncAttributeMaxDynamicSharedMemorySize, SMEM_TOT);
    cudaFuncSetAttribute(gemm_mma<false, true,  false, false, false>,
                         cudaFuncAttributeMaxDynamicSharedMemorySize, SMEM_TOT);

    // prep (interleaved with GEMMs so early ncu launch indices hit GEMMs)
    transpose_split<<<dim3(128, 16, 16), 256>>>(x1, x1Th, x1Tl, 512, 4096);  //0
    transpose_split<<<dim3(128, 10, 16), 256>>>(x2, x2Th, x2Tl, 320, 4096);  //1
    split_w<<<512, 256>>>(w_img, wih, wil, 256 * 512);                       //2

    // 1) img = w_img @ x1T  (3-pass); fp32 img + hi/lo split                //3
    gemm_mma<false, true, true, false, true><<<dim3(32, 2, 16), 256, SMEM_TOT>>>(
        wih, wil, x1Th, x1Tl, img, imgh, imgl, nullptr, nullptr, nullptr,
        512, 512, 512, 4096, 0, 0L, 4096L * 512, 256L * 4096, 0L, 1);

    split_w<<<320, 256>>>(w_txt, wth, wtl, 256 * 320);                       //4

    // 2) kv (3-pass): hi/lo [c,n] + transposed hi [n,c]                     //5
    gemm_mma<false, false, true, true, true><<<dim3(32, 2, 16), 256, SMEM_TOT>>>(
        wth, wtl, x2Th, x2Tl, nullptr, kvh, kvl, kvTh, nullptr, nullptr,
        320, 320, 320, 4096, 256, 0L, 4096L * 320, 256L * 4096, 4096L * 256, 1);

    split_w<<<512, 256>>>(w_out, woh, wol, 512 * 256);                       //6

    // 3) logits partials (3-pass, split-K=8)                                //7
    gemm_mma<false, true, false, false, true><<<dim3(2, 2, 16 * NSPLIT), 256, SMEM_TOT>>>(
        imgh, imgl, kvh, kvl, part, nullptr, nullptr, nullptr, nullptr, nullptr,
        NSP / NSPLIT, 4096, 4096, 256, 0,
        256L * 4096, 256L * 4096, 256L * 256, 0L, NSPLIT);

    // 4) softmax                                                            //8
    softmax_rows<<<BATCH * CCH, 256>>>(part, atth, attl);

    // 5) tT[n,c] = gamma*(attn @ kvT) + img  (2-pass, B-lo dropped)         //9
    gemm_mma<true, false, false, true, false><<<dim3(32, 2, 16), 256, SMEM_TOT>>>(
        atth, attl, kvTh, nullptr, nullptr, nullptr, nullptr, tTh, img, gamma,
        256, 256, 256, 4096, 256,
        256L * 256, 4096L * 256, 256L * 4096, 4096L * 256, 1);

    // 6) out = w_out @ tT  (2-pass, B-lo dropped)                           //10
    gemm_mma<false, true, false, false, false><<<dim3(32, 4, 16), 256, SMEM_TOT>>>(
        woh, wol, tTh, nullptr, out, nullptr, nullptr, nullptr, nullptr, nullptr,
        256, 256, 256, 4096, 0,
        0L, 4096L * 256, 512L * 4096, 0L, 1);
}

// round 6
// speedup vs baseline: 3.3298x; 1.0856x over previous
#include <cuda_runtime.h>
#include <cuda_fp16.h>
#include <math.h>

using u32 = unsigned int;

// ===========================================================================
// Problem constants
// ===========================================================================
static const int BATCH  = 16;
static const int CCH    = 256;
static const int NSP    = 4096;
static const int NSPLIT = 8;     // split-K for logits GEMM

// ===========================================================================
// Device scratch (allocation-free)
// ===========================================================================
__device__ __half g_wih[256 * 512], g_wil[256 * 512];
__device__ __half g_wth[256 * 320], g_wtl[256 * 320];
__device__ __half g_woh[512 * 256], g_wol[512 * 256];
__device__ __half g_imgh[(size_t)BATCH * CCH * NSP];
__device__ __half g_imgl[(size_t)BATCH * CCH * NSP];
__device__ __half g_kvh [(size_t)BATCH * CCH * NSP];
__device__ __half g_kvl [(size_t)BATCH * CCH * NSP];
__device__ __half g_kvTh[(size_t)BATCH * NSP * CCH];
__device__ __half g_tTh [(size_t)BATCH * NSP * CCH];
__device__ float  g_part[(size_t)NSPLIT * BATCH * CCH * CCH];
__device__ __half g_atth[(size_t)BATCH * CCH * CCH];
__device__ __half g_attl[(size_t)BATCH * CCH * CCH];

// ===========================================================================
// PTX helpers (base-target ISA: cp.async / ldmatrix / mma.sync)
// ===========================================================================
__device__ __forceinline__ u32 smem_u32(const void* p) {
    u32 a;
    asm("{ .reg .u64 t; cvta.to.shared.u64 t, %1; cvt.u32.u64 %0, t; }"
        : "=r"(a) : "l"(p));
    return a;
}
__device__ __forceinline__ void cp16(u32 dst, const void* src) {
    asm volatile("cp.async.cg.shared.global [%0], [%1], 16;"
                 :: "r"(dst), "l"(src) : "memory");
}
__device__ __forceinline__ void cp_commit() {
    asm volatile("cp.async.commit_group;" ::: "memory");
}
template <int N>
__device__ __forceinline__ void cp_wait() {
    asm volatile("cp.async.wait_group %0;" :: "n"(N) : "memory");
}
#define LDMX4(d0, d1, d2, d3, addr) \
    asm volatile("ldmatrix.sync.aligned.m8n8.x4.shared.b16 {%0,%1,%2,%3},[%4];" \
                 : "=r"(d0), "=r"(d1), "=r"(d2), "=r"(d3) : "r"(addr))
#define MMA16816(c, a, b0, b1) \
    asm volatile("mma.sync.aligned.m16n8k16.row.col.f32.f16.f16.f32 " \
                 "{%0,%1,%2,%3},{%4,%5,%6,%7},{%8,%9},{%0,%1,%2,%3};" \
                 : "+f"((c)[0]), "+f"((c)[1]), "+f"((c)[2]), "+f"((c)[3]) \
                 : "r"((a)[0]), "r"((a)[1]), "r"((a)[2]), "r"((a)[3]), \
                   "r"(b0), "r"(b1))

__device__ __forceinline__ u32 pack2(__half a, __half b) {
    __half2 h = __halves2half2(a, b);
    return *(u32*)&h;
}

// ===========================================================================
// FUSED GEMM (stages 1-2): D[m,n] = sum_k A[m,k] * X[k,n]
// A: pre-split hi/lo fp16 weights, K-major [M,K].
// X: fp32 [K,N] row-major (the raw input) — transposed + hi/lo split on the
// fly: cp.async fp32 staging tile -> convert -> 80B-pitch operand tiles
// (pitch 80 => conflict-free STS.128 / ldmatrix without XOR swizzle).
// 3-pass Markidis: AhBh + AhBl + AlBh. 2-stage tiles, 1-stage fp32 staging.
// WH: write hi/lo fp16 at [m,n].  WHT: write hi fp16 at [n,m] (smem-staged).
// ===========================================================================
static const int FT   = 10240;           // one 128x(64B@80B-pitch) tile
static const int FSTG = 8 * FT;          // fp32 staging offset (81920)
static const int SMEM_F = FSTG + 32 * 528;  // 98816

template <bool WH, bool WHT>
__global__ __launch_bounds__(256, 2)
void gemm_fused(const __half* __restrict__ Ahg, const __half* __restrict__ Alg,
                const float* __restrict__ Xf,
                __half* __restrict__ CHh, __half* __restrict__ CHl,
                __half* __restrict__ CTh,
                int K, int ldC, int ldT, long xBat, long cBat, long tBat)
{
    extern __shared__ __align__(128) char sm[];
    const u32 smb = smem_u32(sm);
    const int tid = threadIdx.x;
    const int wid = tid >> 5;
    const int lid = tid & 31;
    const int wm  = wid >> 2;
    const int wn  = wid & 3;

    const int b  = blockIdx.z;
    const int m0 = blockIdx.y * 128;
    const int n0 = blockIdx.x * 128;

    const __half* Ahm = Ahg + (size_t)m0 * K;
    const __half* Alm = Alg + (size_t)m0 * K;
    const float*  Xb  = Xf + (size_t)b * xBat;

    __half* CHhb = WH  ? (CHh + (size_t)b * cBat) : nullptr;
    __half* CHlb = WH  ? (CHl + (size_t)b * cBat) : nullptr;
    __half* CThb = WHT ? (CTh + (size_t)b * tBat) : nullptr;

    // ldmatrix lane constants (pitch 80, no XOR)
    const int rAl = lid & 15;
    const int ksA = lid >> 4;
    const int rBl = ((lid >> 4) & 1) * 8 + (lid & 7);
    const int csB = (lid >> 3) & 1;

    auto cpA = [&](int chunk, int st) {
        const int kt = chunk * 32;
        #pragma unroll
        for (int t = 0; t < 2; t++) {
            const int task = tid + t * 256;
            const int r = task >> 2, c = task & 3;
            const u32 dst = smb + st * (4 * FT) + r * 80 + c * 16;
            cp16(dst,      Ahm + (size_t)r * K + kt + c * 8);
            cp16(dst + FT, Alm + (size_t)r * K + kt + c * 8);
        }
    };
    auto cpB = [&](int chunk) {
        const int kt = chunk * 32;
        #pragma unroll
        for (int t = 0; t < 4; t++) {
            const int task = tid + t * 256;
            const int kr = task >> 5, c16 = task & 31;
            cp16(smb + FSTG + kr * 528 + c16 * 16,
                 Xb + (size_t)(kt + kr) * ldC + n0 + c16 * 4);
        }
    };
    auto convB = [&](int st) {
        const float* stg = (const float*)(sm + FSTG);
        #pragma unroll
        for (int t = 0; t < 2; t++) {
            const int task = tid + t * 256;
            const int n = task & 127, ko = task >> 7;   // ko 0..3
            float f[8];
            #pragma unroll
            for (int i = 0; i < 8; i++)
                f[i] = stg[(ko * 8 + i) * 132 + n];
            __half h[8], l[8];
            #pragma unroll
            for (int i = 0; i < 8; i++) {
                h[i] = __float2half_rn(f[i]);
                l[i] = __float2half_rn(f[i] - __half2float(h[i]));
            }
            uint4 vh = make_uint4(pack2(h[0], h[1]), pack2(h[2], h[3]),
                                  pack2(h[4], h[5]), pack2(h[6], h[7]));
            uint4 vl = make_uint4(pack2(l[0], l[1]), pack2(l[2], l[3]),
                                  pack2(l[4], l[5]), pack2(l[6], l[7]));
            *(uint4*)(sm + st * (4 * FT) + 2 * FT + n * 80 + ko * 16) = vh;
            *(uint4*)(sm + st * (4 * FT) + 3 * FT + n * 80 + ko * 16) = vl;
        }
    };

    const int nC = K >> 5;

    float acc[4][4][4];
    #pragma unroll
    for (int i = 0; i < 4; i++)
        #pragma unroll
        for (int j = 0; j < 4; j++)
            #pragma unroll
            for (int q = 0; q < 4; q++) acc[i][j][q] = 0.0f;

    // prologue
    cpA(0, 0); cpB(0); cp_commit();
    cp_wait<0>(); __syncthreads();
    convB(0);
    __syncthreads();
    cpA(1, 1); cpB(1); cp_commit();

    for (int c = 0; c < nC; c++) {
        const int st = c & 1;
        const u32 tb = smb + st * (4 * FT);
        #pragma unroll
        for (int s16 = 0; s16 < 2; s16++) {
            u32 bh[8], bl[8];
            const u32 rb = (u32)((wn * 32 + rBl) * 80 + (2 * s16 + csB) * 16);
            LDMX4(bh[0], bh[1], bh[2], bh[3], tb + 2 * FT + rb);
            LDMX4(bh[4], bh[5], bh[6], bh[7], tb + 2 * FT + rb + 1280);
            LDMX4(bl[0], bl[1], bl[2], bl[3], tb + 3 * FT + rb);
            LDMX4(bl[4], bl[5], bl[6], bl[7], tb + 3 * FT + rb + 1280);
            #pragma unroll
            for (int mt = 0; mt < 4; mt++) {
                u32 ah[4], al[4];
                const u32 ra = (u32)((wm * 64 + mt * 16 + rAl) * 80 +
                                     (2 * s16 + ksA) * 16);
                LDMX4(ah[0], ah[1], ah[2], ah[3], tb + ra);
                LDMX4(al[0], al[1], al[2], al[3], tb + FT + ra);
                #pragma unroll
                for (int nt = 0; nt < 4; nt++) {
                    MMA16816(acc[mt][nt], ah, bh[2*nt], bh[2*nt+1]);
                    MMA16816(acc[mt][nt], ah, bl[2*nt], bl[2*nt+1]);
                    MMA16816(acc[mt][nt], al, bh[2*nt], bh[2*nt+1]);
                }
            }
        }
        if (c + 1 < nC) {
            cp_wait<0>(); __syncthreads();   // chunk c+1 arrived; LDSM of c done
            convB(st ^ 1);
            __syncthreads();                 // converts visible; staging free
            if (c + 2 < nC) { cpA(c + 2, st); cpB(c + 2); cp_commit(); }
        }
    }

    // epilogue
    __syncthreads();
    __half* T = (__half*)sm;   // [128 n][136 m] transpose buffer (WHT)
    #pragma unroll
    for (int mt = 0; mt < 4; mt++) {
        #pragma unroll
        for (int nt = 0; nt < 4; nt++) {
            const int nn = wn * 32 + nt * 8 + (lid & 3) * 2;
            #pragma unroll
            for (int h = 0; h < 2; h++) {
                const int ml = wm * 64 + mt * 16 + (lid >> 2) + h * 8;
                const int mm = m0 + ml;
                const float v0 = acc[mt][nt][2 * h];
                const float v1 = acc[mt][nt][2 * h + 1];
                const __half h0 = __float2half_rn(v0);
                const __half h1 = __float2half_rn(v1);
                if (WH) {
                    const __half e0 = __float2half_rn(v0 - __half2float(h0));
                    const __half e1 = __float2half_rn(v1 - __half2float(h1));
                    *(__half2*)(CHhb + (size_t)mm * ldC + n0 + nn) =
                        __halves2half2(h0, h1);
                    *(__half2*)(CHlb + (size_t)mm * ldC + n0 + nn) =
                        __halves2half2(e0, e1);
                }
                if (WHT) {
                    T[(size_t)nn * 136 + ml]       = h0;
                    T[(size_t)(nn + 1) * 136 + ml] = h1;
                }
            }
        }
    }
    if (WHT) {
        __syncthreads();
        #pragma unroll
        for (int it = 0; it < 8; it++) {
            const int idx = it * 256 + tid;
            const int n  = idx >> 4;
            const int ck = idx & 15;
            const uint4 v = *(const uint4*)(T + (size_t)n * 136 + ck * 8);
            *(uint4*)(CThb + (size_t)(n0 + n) * ldT + m0 + ck * 8) = v;
        }
    }
}

// ===========================================================================
// PURE fp16 GEMM (stages 3,5,6) — unchanged from R5 except the residual now
// reconstructs fp32 as hi+lo from two fp16 arrays.
// ===========================================================================
static const int SMEM_STG = 32768;
static const int SMEM_TOT = 3 * SMEM_STG;

template <bool RESID, bool WN, bool WHT, bool PB>
__global__ __launch_bounds__(256, 2)
void gemm_mma(const __half* __restrict__ Ahg, const __half* __restrict__ Alg,
              const __half* __restrict__ Bhg, const __half* __restrict__ Blg,
              float* __restrict__ Cn, __half* __restrict__ CTh,
              const __half* __restrict__ Rhg, const __half* __restrict__ Rlg,
              const float* __restrict__ gamma,
              int K, int ldA, int ldB, int ldC, int ldT,
              long aBat, long bBat, long cBat, long tBat, int nsplit)
{
    extern __shared__ __align__(128) char sm[];
    const u32 smb = smem_u32(sm);
    const int tid = threadIdx.x;
    const int wid = tid >> 5;
    const int lid = tid & 31;
    const int wm  = wid >> 2;
    const int wn  = wid & 3;

    const int z = blockIdx.z;
    const int b = z / nsplit;
    const int s = z - b * nsplit;
    const int nbat = gridDim.z / nsplit;

    const __half* Ah = Ahg + (size_t)b * aBat + (size_t)s * K;
    const __half* Al = Alg + (size_t)b * aBat + (size_t)s * K;
    const __half* Bh = Bhg + (size_t)b * bBat + (size_t)s * K;
    const __half* Bl = PB ? (Blg + (size_t)b * bBat + (size_t)s * K) : nullptr;

    const size_t ob = (size_t)s * nbat + b;
    float*  Cb   = WN  ? (Cn  + ob * cBat) : nullptr;
    __half* CThb = WHT ? (CTh + ob * tBat) : nullptr;
    const __half* Rh = RESID ? (Rhg + (size_t)b * cBat) : nullptr;
    const __half* Rl = RESID ? (Rlg + (size_t)b * cBat) : nullptr;

    const int m0 = blockIdx.y * 128;
    const int n0 = blockIdx.x * 128;

    const __half* Ahm = Ah + (size_t)m0 * ldA;
    const __half* Alm = Al + (size_t)m0 * ldA;
    const __half* Bhn = Bh + (size_t)n0 * ldB;
    const __half* Bln = PB ? (Bl + (size_t)n0 * ldB) : nullptr;

    const int rAl = lid & 15;
    const int ksA = lid >> 4;
    const int xA  = (rAl >> 1) & 3;
    const int rBl = ((lid >> 4) & 1) * 8 + (lid & 7);
    const int csB = (lid >> 3) & 1;
    const int xB  = (rBl >> 1) & 3;

    auto ldStage = [&](int chunk, int stg) {
        const u32 sb = smb + stg * SMEM_STG;
        const int kt = chunk * 32;
        #pragma unroll
        for (int p = 0; p < 2; p++) {
            const int idx = tid + p * 256;
            const int r = idx >> 2;
            const int c = idx & 3;
            const u32 soff = r * 64 + ((c ^ ((r >> 1) & 3)) << 4);
            const size_t ga = (size_t)r * ldA + kt + c * 8;
            const size_t gb = (size_t)r * ldB + kt + c * 8;
            cp16(sb + soff,          Ahm + ga);
            cp16(sb + 8192 + soff,   Alm + ga);
            cp16(sb + 16384 + soff,  Bhn + gb);
            if constexpr (PB) cp16(sb + 24576 + soff, Bln + gb);
        }
    };

    const int nC = K >> 5;

    float acc[4][4][4];
    #pragma unroll
    for (int i = 0; i < 4; i++)
        #pragma unroll
        for (int j = 0; j < 4; j++)
            #pragma unroll
            for (int q = 0; q < 4; q++) acc[i][j][q] = 0.0f;

    ldStage(0, 0); cp_commit();
    ldStage(1, 1); cp_commit();

    for (int c = 0; c < nC; c++) {
        if (c + 1 < nC) cp_wait<1>(); else cp_wait<0>();
        __syncthreads();
        if (c + 2 < nC) { ldStage(c + 2, (c + 2) % 3); cp_commit(); }

        const u32 tb = smb + (c % 3) * SMEM_STG;
        #pragma unroll
        for (int s16 = 0; s16 < 2; s16++) {
            u32 bh[8], bl[8];
            const u32 rb = (u32)((wn * 32 + rBl) * 64 +
                                 (((2 * s16 + csB) ^ xB) << 4));
            LDMX4(bh[0], bh[1], bh[2], bh[3], tb + 16384 + rb);
            LDMX4(bh[4], bh[5], bh[6], bh[7], tb + 16384 + rb + 1024);
            if constexpr (PB) {
                LDMX4(bl[0], bl[1], bl[2], bl[3], tb + 24576 + rb);
                LDMX4(bl[4], bl[5], bl[6], bl[7], tb + 24576 + rb + 1024);
            }
            #pragma unroll
            for (int mt = 0; mt < 4; mt++) {
                u32 ah[4], al[4];
                const u32 ra = (u32)((wm * 64 + mt * 16 + rAl) * 64 +
                                     (((2 * s16 + ksA) ^ xA) << 4));
                LDMX4(ah[0], ah[1], ah[2], ah[3], tb + ra);
                LDMX4(al[0], al[1], al[2], al[3], tb + 8192 + ra);
                #pragma unroll
                for (int nt = 0; nt < 4; nt++) {
                    MMA16816(acc[mt][nt], ah, bh[2*nt], bh[2*nt+1]);
                    if constexpr (PB)
                        MMA16816(acc[mt][nt], ah, bl[2*nt], bl[2*nt+1]);
                    MMA16816(acc[mt][nt], al, bh[2*nt], bh[2*nt+1]);
                }
            }
        }
    }

    // epilogue
    if (WHT) __syncthreads();
    __half* T = (__half*)sm;

    const float gm = RESID ? gamma[0] : 0.0f;
    #pragma unroll
    for (int mt = 0; mt < 4; mt++) {
        #pragma unroll
        for (int nt = 0; nt < 4; nt++) {
            const int nn = wn * 32 + nt * 8 + (lid & 3) * 2;
            #pragma unroll
            for (int h = 0; h < 2; h++) {
                const int ml = wm * 64 + mt * 16 + (lid >> 2) + h * 8;
                const int mm = m0 + ml;
                float v0 = acc[mt][nt][2 * h];
                float v1 = acc[mt][nt][2 * h + 1];
                if (RESID) {
                    const size_t off = (size_t)mm * ldC + n0 + nn;
                    const __half2 rh = *(const __half2*)(Rh + off);
                    const __half2 rl = *(const __half2*)(Rl + off);
                    v0 = gm * v0 + __low2float(rh)  + __low2float(rl);
                    v1 = gm * v1 + __high2float(rh) + __high2float(rl);
                }
                if (WN)
                    *(float2*)(Cb + (size_t)mm * ldC + n0 + nn) =
                        make_float2(v0, v1);
                if (WHT) {
                    T[(size_t)nn * 136 + ml]       = __float2half_rn(v0);
                    T[(size_t)(nn + 1) * 136 + ml] = __float2half_rn(v1);
                }
            }
        }
    }

    if (WHT) {
        __syncthreads();
        #pragma unroll
        for (int it = 0; it < 8; it++) {
            const int idx = it * 256 + tid;
            const int n  = idx >> 4;
            const int ck = idx & 15;
            const uint4 v = *(const uint4*)(T + (size_t)n * 136 + ck * 8);
            *(uint4*)(CThb + (size_t)(n0 + n) * ldT + m0 + ck * 8) = v;
        }
    }
}

// ===========================================================================
// fp32 -> fp16 hi/lo split (weights)
// ===========================================================================
__global__ __launch_bounds__(256)
void split_w(const float* __restrict__ in, __half* __restrict__ oh,
             __half* __restrict__ ol, int n)
{
    const int i = blockIdx.x * 256 + threadIdx.x;
    if (i < n) {
        const float v = in[i];
        const __half hh = __float2half_rn(v);
        oh[i] = hh;
        ol[i] = __float2half_rn(v - __half2float(hh));
    }
}

// ===========================================================================
// Softmax over rows of 256 (sums NSPLIT split-K partials), emits hi/lo fp16.
// ===========================================================================
__global__ __launch_bounds__(256)
void softmax_rows(const float* __restrict__ P, __half* __restrict__ Ah,
                  __half* __restrict__ Al)
{
    const size_t RS = (size_t)BATCH * CCH * CCH;
    const int row = blockIdx.x;
    const int tid = threadIdx.x;
    const size_t base = (size_t)row * CCH + tid;
    float x = 0.0f;
    #pragma unroll
    for (int s = 0; s < NSPLIT; s++) x += P[s * RS + base];

    __shared__ float red[256];
    red[tid] = x;
    __syncthreads();
    for (int o = 128; o > 0; o >>= 1) {
        if (tid < o) red[tid] = fmaxf(red[tid], red[tid + o]);
        __syncthreads();
    }
    const float mx = red[0];
    __syncthreads();
    const float e = expf(x - mx);
    red[tid] = e;
    __syncthreads();
    for (int o = 128; o > 0; o >>= 1) {
        if (tid < o) red[tid] += red[tid + o];
        __syncthreads();
    }
    const float p = e / red[0];
    const __half hh = __float2half_rn(p);
    Ah[base] = hh;
    Al[base] = __float2half_rn(p - __half2float(hh));
}

// ===========================================================================
// Launch
// ===========================================================================
extern "C" void kernel_launch(void* const* d_in, const int* in_sizes, int n_in,
                              void* d_out, int out_size)
{
    const float* x1    = (const float*)d_in[0];
    const float* x2    = (const float*)d_in[1];
    const float* w_img = (const float*)d_in[2];
    const float* w_txt = (const float*)d_in[3];
    const float* w_out = (const float*)d_in[4];
    const float* gamma = (const float*)d_in[5];
    float* out = (float*)d_out;

    __half *wih, *wil, *wth, *wtl, *woh, *wol;
    __half *imgh, *imgl, *kvh, *kvl, *kvTh, *tTh, *atth, *attl;
    float *part;
    cudaGetSymbolAddress((void**)&wih,  g_wih);
    cudaGetSymbolAddress((void**)&wil,  g_wil);
    cudaGetSymbolAddress((void**)&wth,  g_wth);
    cudaGetSymbolAddress((void**)&wtl,  g_wtl);
    cudaGetSymbolAddress((void**)&woh,  g_woh);
    cudaGetSymbolAddress((void**)&wol,  g_wol);
    cudaGetSymbolAddress((void**)&imgh, g_imgh);
    cudaGetSymbolAddress((void**)&imgl, g_imgl);
    cudaGetSymbolAddress((void**)&kvh,  g_kvh);
    cudaGetSymbolAddress((void**)&kvl,  g_kvl);
    cudaGetSymbolAddress((void**)&kvTh, g_kvTh);
    cudaGetSymbolAddress((void**)&tTh,  g_tTh);
    cudaGetSymbolAddress((void**)&part, g_part);
    cudaGetSymbolAddress((void**)&atth, g_atth);
    cudaGetSymbolAddress((void**)&attl, g_attl);

    cudaFuncSetAttribute(gemm_fused<true, false>,
                         cudaFuncAttributeMaxDynamicSharedMemorySize, SMEM_F);
    cudaFuncSetAttribute(gemm_fused<true, true>,
                         cudaFuncAttributeMaxDynamicSharedMemorySize, SMEM_F);
    cudaFuncSetAttribute(gemm_mma<false, true,  false, true >,
                         cudaFuncAttributeMaxDynamicSharedMemorySize, SMEM_TOT);
    cudaFuncSetAttribute(gemm_mma<true,  false, true,  false>,
                         cudaFuncAttributeMaxDynamicSharedMemorySize, SMEM_TOT);
    cudaFuncSetAttribute(gemm_mma<false, true,  false, false>,
                         cudaFuncAttributeMaxDynamicSharedMemorySize, SMEM_TOT);

    // weight splits                                                         //0-2
    split_w<<<512, 256>>>(w_img, wih, wil, 256 * 512);
    split_w<<<320, 256>>>(w_txt, wth, wtl, 256 * 320);
    split_w<<<512, 256>>>(w_out, woh, wol, 512 * 256);

    // 1) img = w_img @ x1 (fused transpose+split of x1); out imgh/imgl      //3
    gemm_fused<true, false><<<dim3(32, 2, 16), 256, SMEM_F>>>(
        wih, wil, x1, imgh, imgl, nullptr,
        512, 4096, 0, 512L * 4096, 256L * 4096, 0L);

    // 2) kv = w_txt @ x2 (fused); out kvh/kvl + transposed kvTh             //4
    gemm_fused<true, true><<<dim3(32, 2, 16), 256, SMEM_F>>>(
        wth, wtl, x2, kvh, kvl, kvTh,
        320, 4096, 256, 320L * 4096, 256L * 4096, 4096L * 256);

    // 3) logits partials (3-pass, split-K=8)                                //5
    gemm_mma<false, true, false, true><<<dim3(2, 2, 16 * NSPLIT), 256, SMEM_TOT>>>(
        imgh, imgl, kvh, kvl, part, nullptr, nullptr, nullptr, nullptr,
        NSP / NSPLIT, 4096, 4096, 256, 0,
        256L * 4096, 256L * 4096, 256L * 256, 0L, NSPLIT);

    // 4) softmax                                                            //6
    softmax_rows<<<BATCH * CCH, 256>>>(part, atth, attl);

    // 5) tT[n,c] = gamma*(attn @ kvT) + (imgh+imgl)  (2-pass), WHT          //7
    gemm_mma<true, false, true, false><<<dim3(32, 2, 16), 256, SMEM_TOT>>>(
        atth, attl, kvTh, nullptr, nullptr, tTh, imgh, imgl, gamma,
        256, 256, 256, 4096, 256,
        256L * 256, 4096L * 256, 256L * 4096, 4096L * 256, 1);

    // 6) out = w_out @ tT  (2-pass)                                         //8
    gemm_mma<false, true, false, false><<<dim3(32, 4, 16), 256, SMEM_TOT>>>(
        woh, wol, tTh, nullptr, out, nullptr, nullptr, nullptr, nullptr,
        256, 256, 256, 4096, 0,
        0L, 4096L * 256, 512L * 4096, 0L, 1);
}

// round 7
// speedup vs baseline: 3.3824x; 1.0158x over previous
#include <cuda_runtime.h>
#include <cuda_fp16.h>
#include <math.h>

using u32 = unsigned int;

// ===========================================================================
// Problem constants
// ===========================================================================
static const int BATCH  = 16;
static const int CCH    = 256;
static const int NSP    = 4096;
static const int NSPLIT = 8;     // split-K for logits GEMM

// ===========================================================================
// Device scratch (allocation-free)
// ===========================================================================
__device__ __half g_wih[256 * 512], g_wil[256 * 512];
__device__ __half g_wth[256 * 320], g_wtl[256 * 320];
__device__ __half g_woh[512 * 256], g_wol[512 * 256];
__device__ __half g_imgh[(size_t)BATCH * CCH * NSP];
__device__ __half g_imgl[(size_t)BATCH * CCH * NSP];
__device__ __half g_kvh [(size_t)BATCH * CCH * NSP];
__device__ __half g_kvl [(size_t)BATCH * CCH * NSP];
__device__ __half g_kvTh[(size_t)BATCH * NSP * CCH];
__device__ __half g_tTh [(size_t)BATCH * NSP * CCH];
__device__ float  g_part[(size_t)NSPLIT * BATCH * CCH * CCH];
__device__ __half g_atth[(size_t)BATCH * CCH * CCH];
__device__ __half g_attl[(size_t)BATCH * CCH * CCH];

// ===========================================================================
// PTX helpers (base-target ISA: cp.async / ldmatrix / mma.sync)
// ===========================================================================
__device__ __forceinline__ u32 smem_u32(const void* p) {
    u32 a;
    asm("{ .reg .u64 t; cvta.to.shared.u64 t, %1; cvt.u32.u64 %0, t; }"
        : "=r"(a) : "l"(p));
    return a;
}
__device__ __forceinline__ void cp16(u32 dst, const void* src) {
    asm volatile("cp.async.cg.shared.global [%0], [%1], 16;"
                 :: "r"(dst), "l"(src) : "memory");
}
__device__ __forceinline__ void cp_commit() {
    asm volatile("cp.async.commit_group;" ::: "memory");
}
template <int N>
__device__ __forceinline__ void cp_wait() {
    asm volatile("cp.async.wait_group %0;" :: "n"(N) : "memory");
}
#define LDMX4(d0, d1, d2, d3, addr) \
    asm volatile("ldmatrix.sync.aligned.m8n8.x4.shared.b16 {%0,%1,%2,%3},[%4];" \
                 : "=r"(d0), "=r"(d1), "=r"(d2), "=r"(d3) : "r"(addr))
#define MMA16816(c, a, b0, b1) \
    asm volatile("mma.sync.aligned.m16n8k16.row.col.f32.f16.f16.f32 " \
                 "{%0,%1,%2,%3},{%4,%5,%6,%7},{%8,%9},{%0,%1,%2,%3};" \
                 : "+f"((c)[0]), "+f"((c)[1]), "+f"((c)[2]), "+f"((c)[3]) \
                 : "r"((a)[0]), "r"((a)[1]), "r"((a)[2]), "r"((a)[3]), \
                   "r"(b0), "r"(b1))

__device__ __forceinline__ u32 pack2(__half a, __half b) {
    __half2 h = __halves2half2(a, b);
    return *(u32*)&h;
}

// ===========================================================================
// FUSED GEMM (stages 1-2): D[m,n] = sum_k A[m,k] * X[k,n]
// A: pre-split hi/lo fp16 weights, K-major [M,K].
// X: fp32 [K,N] row-major — transposed + hi/lo split on the fly.
// DOUBLE staging buffers: cpB(c+2) issues BEFORE MMA(c) so the big fp32 load
// is covered by a full MMA block + convert; cpA (tiny, L2-hot) issues late.
// 3-pass Markidis. Operand tiles pitch 80B (conflict-free, no XOR).
// WH: write hi/lo fp16 at [m,n].  WHT: write hi fp16 at [n,m] (smem-staged).
// ===========================================================================
static const int FT   = 10240;              // one 128x(64B@80B-pitch) tile
static const int FSTG = 8 * FT;             // 81920: staging area offset
static const int SMEM_F = FSTG + 2 * 16384; // 114688

template <bool WH, bool WHT>
__global__ __launch_bounds__(256, 2)
void gemm_fused(const __half* __restrict__ Ahg, const __half* __restrict__ Alg,
                const float* __restrict__ Xf,
                __half* __restrict__ CHh, __half* __restrict__ CHl,
                __half* __restrict__ CTh,
                int K, int ldC, int ldT, long xBat, long cBat, long tBat)
{
    extern __shared__ __align__(128) char sm[];
    const u32 smb = smem_u32(sm);
    const int tid = threadIdx.x;
    const int wid = tid >> 5;
    const int lid = tid & 31;
    const int wm  = wid >> 2;
    const int wn  = wid & 3;

    const int b  = blockIdx.z;
    const int m0 = blockIdx.y * 128;
    const int n0 = blockIdx.x * 128;

    const __half* Ahm = Ahg + (size_t)m0 * K;
    const __half* Alm = Alg + (size_t)m0 * K;
    const float*  Xb  = Xf + (size_t)b * xBat;

    __half* CHhb = WH  ? (CHh + (size_t)b * cBat) : nullptr;
    __half* CHlb = WH  ? (CHl + (size_t)b * cBat) : nullptr;
    __half* CThb = WHT ? (CTh + (size_t)b * tBat) : nullptr;

    const int rAl = lid & 15;
    const int ksA = lid >> 4;
    const int rBl = ((lid >> 4) & 1) * 8 + (lid & 7);
    const int csB = (lid >> 3) & 1;

    auto cpA = [&](int chunk, int st) {
        const int kt = chunk * 32;
        #pragma unroll
        for (int t = 0; t < 2; t++) {
            const int task = tid + t * 256;
            const int r = task >> 2, c = task & 3;
            const u32 dst = smb + st * (4 * FT) + r * 80 + c * 16;
            cp16(dst,      Ahm + (size_t)r * K + kt + c * 8);
            cp16(dst + FT, Alm + (size_t)r * K + kt + c * 8);
        }
    };
    auto cpB = [&](int chunk) {
        const int kt = chunk * 32;
        const u32 dst0 = smb + FSTG + (chunk & 1) * 16384;
        #pragma unroll
        for (int t = 0; t < 4; t++) {
            const int task = tid + t * 256;
            const int kr = task >> 5, c16 = task & 31;
            cp16(dst0 + kr * 512 + c16 * 16,
                 Xb + (size_t)(kt + kr) * ldC + n0 + c16 * 4);
        }
    };
    auto convB = [&](int chunk) {
        const int st = chunk & 1;
        const float* stg = (const float*)(sm + FSTG + st * 16384);
        #pragma unroll
        for (int t = 0; t < 2; t++) {
            const int task = tid + t * 256;
            const int n = task & 127, ko = task >> 7;
            float f[8];
            #pragma unroll
            for (int i = 0; i < 8; i++)
                f[i] = stg[(ko * 8 + i) * 128 + n];
            __half h[8], l[8];
            #pragma unroll
            for (int i = 0; i < 8; i++) {
                h[i] = __float2half_rn(f[i]);
                l[i] = __float2half_rn(f[i] - __half2float(h[i]));
            }
            uint4 vh = make_uint4(pack2(h[0], h[1]), pack2(h[2], h[3]),
                                  pack2(h[4], h[5]), pack2(h[6], h[7]));
            uint4 vl = make_uint4(pack2(l[0], l[1]), pack2(l[2], l[3]),
                                  pack2(l[4], l[5]), pack2(l[6], l[7]));
            *(uint4*)(sm + st * (4 * FT) + 2 * FT + n * 80 + ko * 16) = vh;
            *(uint4*)(sm + st * (4 * FT) + 3 * FT + n * 80 + ko * 16) = vl;
        }
    };

    const int nC = K >> 5;

    float acc[4][4][4];
    #pragma unroll
    for (int i = 0; i < 4; i++)
        #pragma unroll
        for (int j = 0; j < 4; j++)
            #pragma unroll
            for (int q = 0; q < 4; q++) acc[i][j][q] = 0.0f;

    // prologue: chunks 0,1 (A+B joint groups)
    cpA(0, 0); cpB(0); cp_commit();
    cpA(1, 1); cpB(1); cp_commit();
    cp_wait<1>(); __syncthreads();
    convB(0);
    __syncthreads();

    for (int c = 0; c < nC; c++) {
        const int st = c & 1;
        const u32 tb = smb + st * (4 * FT);
        if (c + 2 < nC) { cpB(c + 2); cp_commit(); }   // early: staging c&1 free
        #pragma unroll
        for (int s16 = 0; s16 < 2; s16++) {
            u32 bh[8], bl[8];
            const u32 rb = (u32)((wn * 32 + rBl) * 80 + (2 * s16 + csB) * 16);
            LDMX4(bh[0], bh[1], bh[2], bh[3], tb + 2 * FT + rb);
            LDMX4(bh[4], bh[5], bh[6], bh[7], tb + 2 * FT + rb + 1280);
            LDMX4(bl[0], bl[1], bl[2], bl[3], tb + 3 * FT + rb);
            LDMX4(bl[4], bl[5], bl[6], bl[7], tb + 3 * FT + rb + 1280);
            #pragma unroll
            for (int mt = 0; mt < 4; mt++) {
                u32 ah[4], al[4];
                const u32 ra = (u32)((wm * 64 + mt * 16 + rAl) * 80 +
                                     (2 * s16 + ksA) * 16);
                LDMX4(ah[0], ah[1], ah[2], ah[3], tb + ra);
                LDMX4(al[0], al[1], al[2], al[3], tb + FT + ra);
                #pragma unroll
                for (int nt = 0; nt < 4; nt++) {
                    MMA16816(acc[mt][nt], ah, bh[2*nt], bh[2*nt+1]);
                    MMA16816(acc[mt][nt], ah, bl[2*nt], bl[2*nt+1]);
                    MMA16816(acc[mt][nt], al, bh[2*nt], bh[2*nt+1]);
                }
            }
        }
        if (c + 1 < nC) {
            if (c + 2 < nC) cp_wait<1>(); else cp_wait<0>();
            __syncthreads();
            convB(c + 1);
            __syncthreads();
            if (c + 2 < nC) { cpA(c + 2, st); cp_commit(); }
        }
    }

    // epilogue
    __syncthreads();
    __half* T = (__half*)sm;   // [128 n][136 m] transpose buffer (WHT)
    #pragma unroll
    for (int mt = 0; mt < 4; mt++) {
        #pragma unroll
        for (int nt = 0; nt < 4; nt++) {
            const int nn = wn * 32 + nt * 8 + (lid & 3) * 2;
            #pragma unroll
            for (int h = 0; h < 2; h++) {
                const int ml = wm * 64 + mt * 16 + (lid >> 2) + h * 8;
                const int mm = m0 + ml;
                const float v0 = acc[mt][nt][2 * h];
                const float v1 = acc[mt][nt][2 * h + 1];
                const __half h0 = __float2half_rn(v0);
                const __half h1 = __float2half_rn(v1);
                if (WH) {
                    const __half e0 = __float2half_rn(v0 - __half2float(h0));
                    const __half e1 = __float2half_rn(v1 - __half2float(h1));
                    *(__half2*)(CHhb + (size_t)mm * ldC + n0 + nn) =
                        __halves2half2(h0, h1);
                    *(__half2*)(CHlb + (size_t)mm * ldC + n0 + nn) =
                        __halves2half2(e0, e1);
                }
                if (WHT) {
                    T[(size_t)nn * 136 + ml]       = h0;
                    T[(size_t)(nn + 1) * 136 + ml] = h1;
                }
            }
        }
    }
    if (WHT) {
        __syncthreads();
        #pragma unroll
        for (int it = 0; it < 8; it++) {
            const int idx = it * 256 + tid;
            const int n  = idx >> 4;
            const int ck = idx & 15;
            const uint4 v = *(const uint4*)(T + (size_t)n * 136 + ck * 8);
            *(uint4*)(CThb + (size_t)(n0 + n) * ldT + m0 + ck * 8) = v;
        }
    }
}

// ===========================================================================
// PURE fp16 GEMM (stages 3,5,6).
// PB=true : 3-pass, 3 stages x 32KB.  PB=false: 2-pass, 4 stages x 24KB.
// ===========================================================================
static const int SMEM_TOT = 98304;

template <bool RESID, bool WN, bool WHT, bool PB>
__global__ __launch_bounds__(256, 2)
void gemm_mma(const __half* __restrict__ Ahg, const __half* __restrict__ Alg,
              const __half* __restrict__ Bhg, const __half* __restrict__ Blg,
              float* __restrict__ Cn, __half* __restrict__ CTh,
              const __half* __restrict__ Rhg, const __half* __restrict__ Rlg,
              const float* __restrict__ gamma,
              int K, int ldA, int ldB, int ldC, int ldT,
              long aBat, long bBat, long cBat, long tBat, int nsplit)
{
    constexpr int NST    = PB ? 3 : 4;
    constexpr int STRIDE = PB ? 32768 : 24576;

    extern __shared__ __align__(128) char sm[];
    const u32 smb = smem_u32(sm);
    const int tid = threadIdx.x;
    const int wid = tid >> 5;
    const int lid = tid & 31;
    const int wm  = wid >> 2;
    const int wn  = wid & 3;

    const int z = blockIdx.z;
    const int b = z / nsplit;
    const int s = z - b * nsplit;
    const int nbat = gridDim.z / nsplit;

    const __half* Ah = Ahg + (size_t)b * aBat + (size_t)s * K;
    const __half* Al = Alg + (size_t)b * aBat + (size_t)s * K;
    const __half* Bh = Bhg + (size_t)b * bBat + (size_t)s * K;
    const __half* Bl = PB ? (Blg + (size_t)b * bBat + (size_t)s * K) : nullptr;

    const size_t ob = (size_t)s * nbat + b;
    float*  Cb   = WN  ? (Cn  + ob * cBat) : nullptr;
    __half* CThb = WHT ? (CTh + ob * tBat) : nullptr;
    const __half* Rh = RESID ? (Rhg + (size_t)b * cBat) : nullptr;
    const __half* Rl = RESID ? (Rlg + (size_t)b * cBat) : nullptr;

    const int m0 = blockIdx.y * 128;
    const int n0 = blockIdx.x * 128;

    const __half* Ahm = Ah + (size_t)m0 * ldA;
    const __half* Alm = Al + (size_t)m0 * ldA;
    const __half* Bhn = Bh + (size_t)n0 * ldB;
    const __half* Bln = PB ? (Bl + (size_t)n0 * ldB) : nullptr;

    const int rAl = lid & 15;
    const int ksA = lid >> 4;
    const int xA  = (rAl >> 1) & 3;
    const int rBl = ((lid >> 4) & 1) * 8 + (lid & 7);
    const int csB = (lid >> 3) & 1;
    const int xB  = (rBl >> 1) & 3;

    auto ldStage = [&](int chunk, int stg) {
        const u32 sb = smb + stg * STRIDE;
        const int kt = chunk * 32;
        #pragma unroll
        for (int p = 0; p < 2; p++) {
            const int idx = tid + p * 256;
            const int r = idx >> 2;
            const int c = idx & 3;
            const u32 soff = r * 64 + ((c ^ ((r >> 1) & 3)) << 4);
            const size_t ga = (size_t)r * ldA + kt + c * 8;
            const size_t gb = (size_t)r * ldB + kt + c * 8;
            cp16(sb + soff,          Ahm + ga);
            cp16(sb + 8192 + soff,   Alm + ga);
            cp16(sb + 16384 + soff,  Bhn + gb);
            if constexpr (PB) cp16(sb + 24576 + soff, Bln + gb);
        }
    };

    const int nC = K >> 5;

    float acc[4][4][4];
    #pragma unroll
    for (int i = 0; i < 4; i++)
        #pragma unroll
        for (int j = 0; j < 4; j++)
            #pragma unroll
            for (int q = 0; q < 4; q++) acc[i][j][q] = 0.0f;

    #pragma unroll
    for (int p = 0; p < NST - 1; p++) { ldStage(p, p); cp_commit(); }

    for (int c = 0; c < nC; c++) {
        const int rem = nC - 1 - c;
        if constexpr (PB) {
            if (rem >= 1) cp_wait<1>(); else cp_wait<0>();
        } else {
            if (rem >= 2) cp_wait<2>();
            else if (rem == 1) cp_wait<1>();
            else cp_wait<0>();
        }
        __syncthreads();
        if (c + NST - 1 < nC) { ldStage(c + NST - 1, (c + NST - 1) % NST); cp_commit(); }

        const u32 tb = smb + (c % NST) * STRIDE;
        #pragma unroll
        for (int s16 = 0; s16 < 2; s16++) {
            u32 bh[8], bl[8];
            const u32 rb = (u32)((wn * 32 + rBl) * 64 +
                                 (((2 * s16 + csB) ^ xB) << 4));
            LDMX4(bh[0], bh[1], bh[2], bh[3], tb + 16384 + rb);
            LDMX4(bh[4], bh[5], bh[6], bh[7], tb + 16384 + rb + 1024);
            if constexpr (PB) {
                LDMX4(bl[0], bl[1], bl[2], bl[3], tb + 24576 + rb);
                LDMX4(bl[4], bl[5], bl[6], bl[7], tb + 24576 + rb + 1024);
            }
            #pragma unroll
            for (int mt = 0; mt < 4; mt++) {
                u32 ah[4], al[4];
                const u32 ra = (u32)((wm * 64 + mt * 16 + rAl) * 64 +
                                     (((2 * s16 + ksA) ^ xA) << 4));
                LDMX4(ah[0], ah[1], ah[2], ah[3], tb + ra);
                LDMX4(al[0], al[1], al[2], al[3], tb + 8192 + ra);
                #pragma unroll
                for (int nt = 0; nt < 4; nt++) {
                    MMA16816(acc[mt][nt], ah, bh[2*nt], bh[2*nt+1]);
                    if constexpr (PB)
                        MMA16816(acc[mt][nt], ah, bl[2*nt], bl[2*nt+1]);
                    MMA16816(acc[mt][nt], al, bh[2*nt], bh[2*nt+1]);
                }
            }
        }
    }

    // epilogue
    if (WHT) __syncthreads();
    __half* T = (__half*)sm;

    const float gm = RESID ? gamma[0] : 0.0f;
    #pragma unroll
    for (int mt = 0; mt < 4; mt++) {
        #pragma unroll
        for (int nt = 0; nt < 4; nt++) {
            const int nn = wn * 32 + nt * 8 + (lid & 3) * 2;
            #pragma unroll
            for (int h = 0; h < 2; h++) {
                const int ml = wm * 64 + mt * 16 + (lid >> 2) + h * 8;
                const int mm = m0 + ml;
                float v0 = acc[mt][nt][2 * h];
                float v1 = acc[mt][nt][2 * h + 1];
                if (RESID) {
                    const size_t off = (size_t)mm * ldC + n0 + nn;
                    const __half2 rh = *(const __half2*)(Rh + off);
                    const __half2 rl = *(const __half2*)(Rl + off);
                    v0 = gm * v0 + __low2float(rh)  + __low2float(rl);
                    v1 = gm * v1 + __high2float(rh) + __high2float(rl);
                }
                if (WN)
                    *(float2*)(Cb + (size_t)mm * ldC + n0 + nn) =
                        make_float2(v0, v1);
                if (WHT) {
                    T[(size_t)nn * 136 + ml]       = __float2half_rn(v0);
                    T[(size_t)(nn + 1) * 136 + ml] = __float2half_rn(v1);
                }
            }
        }
    }

    if (WHT) {
        __syncthreads();
        #pragma unroll
        for (int it = 0; it < 8; it++) {
            const int idx = it * 256 + tid;
            const int n  = idx >> 4;
            const int ck = idx & 15;
            const uint4 v = *(const uint4*)(T + (size_t)n * 136 + ck * 8);
            *(uint4*)(CThb + (size_t)(n0 + n) * ldT + m0 + ck * 8) = v;
        }
    }
}

// ===========================================================================
// fp32 -> fp16 hi/lo split (weights)
// ===========================================================================
__global__ __launch_bounds__(256)
void split_w(const float* __restrict__ in, __half* __restrict__ oh,
             __half* __restrict__ ol, int n)
{
    const int i = blockIdx.x * 256 + threadIdx.x;
    if (i < n) {
        const float v = in[i];
        const __half hh = __float2half_rn(v);
        oh[i] = hh;
        ol[i] = __float2half_rn(v - __half2float(hh));
    }
}

// ===========================================================================
// Softmax over rows of 256 (sums NSPLIT split-K partials), emits hi/lo fp16.
// ===========================================================================
__global__ __launch_bounds__(256)
void softmax_rows(const float* __restrict__ P, __half* __restrict__ Ah,
                  __half* __restrict__ Al)
{
    const size_t RS = (size_t)BATCH * CCH * CCH;
    const int row = blockIdx.x;
    const int tid = threadIdx.x;
    const size_t base = (size_t)row * CCH + tid;
    float x = 0.0f;
    #pragma unroll
    for (int s = 0; s < NSPLIT; s++) x += P[s * RS + base];

    __shared__ float red[256];
    red[tid] = x;
    __syncthreads();
    for (int o = 128; o > 0; o >>= 1) {
        if (tid < o) red[tid] = fmaxf(red[tid], red[tid + o]);
        __syncthreads();
    }
    const float mx = red[0];
    __syncthreads();
    const float e = expf(x - mx);
    red[tid] = e;
    __syncthreads();
    for (int o = 128; o > 0; o >>= 1) {
        if (tid < o) red[tid] += red[tid + o];
        __syncthreads();
    }
    const float p = e / red[0];
    const __half hh = __float2half_rn(p);
    Ah[base] = hh;
    Al[base] = __float2half_rn(p - __half2float(hh));
}

// ===========================================================================
// Launch
// ===========================================================================
extern "C" void kernel_launch(void* const* d_in, const int* in_sizes, int n_in,
                              void* d_out, int out_size)
{
    const float* x1    = (const float*)d_in[0];
    const float* x2    = (const float*)d_in[1];
    const float* w_img = (const float*)d_in[2];
    const float* w_txt = (const float*)d_in[3];
    const float* w_out = (const float*)d_in[4];
    const float* gamma = (const float*)d_in[5];
    float* out = (float*)d_out;

    __half *wih, *wil, *wth, *wtl, *woh, *wol;
    __half *imgh, *imgl, *kvh, *kvl, *kvTh, *tTh, *atth, *attl;
    float *part;
    cudaGetSymbolAddress((void**)&wih,  g_wih);
    cudaGetSymbolAddress((void**)&wil,  g_wil);
    cudaGetSymbolAddress((void**)&wth,  g_wth);
    cudaGetSymbolAddress((void**)&wtl,  g_wtl);
    cudaGetSymbolAddress((void**)&woh,  g_woh);
    cudaGetSymbolAddress((void**)&wol,  g_wol);
    cudaGetSymbolAddress((void**)&imgh, g_imgh);
    cudaGetSymbolAddress((void**)&imgl, g_imgl);
    cudaGetSymbolAddress((void**)&kvh,  g_kvh);
    cudaGetSymbolAddress((void**)&kvl,  g_kvl);
    cudaGetSymbolAddress((void**)&kvTh, g_kvTh);
    cudaGetSymbolAddress((void**)&tTh,  g_tTh);
    cudaGetSymbolAddress((void**)&part, g_part);
    cudaGetSymbolAddress((void**)&atth, g_atth);
    cudaGetSymbolAddress((void**)&attl, g_attl);

    cudaFuncSetAttribute(gemm_fused<true, false>,
                         cudaFuncAttributeMaxDynamicSharedMemorySize, SMEM_F);
    cudaFuncSetAttribute(gemm_fused<true, true>,
                         cudaFuncAttributeMaxDynamicSharedMemorySize, SMEM_F);
    cudaFuncSetAttribute(gemm_mma<false, true,  false, true >,
                         cudaFuncAttributeMaxDynamicSharedMemorySize, SMEM_TOT);
    cudaFuncSetAttribute(gemm_mma<true,  false, true,  false>,
                         cudaFuncAttributeMaxDynamicSharedMemorySize, SMEM_TOT);
    cudaFuncSetAttribute(gemm_mma<false, true,  false, false>,
                         cudaFuncAttributeMaxDynamicSharedMemorySize, SMEM_TOT);

    // weight splits                                                         //0-2
    split_w<<<512, 256>>>(w_img, wih, wil, 256 * 512);
    split_w<<<320, 256>>>(w_txt, wth, wtl, 256 * 320);
    split_w<<<512, 256>>>(w_out, woh, wol, 512 * 256);

    // 1) img = w_img @ x1 (fused transpose+split of x1); out imgh/imgl      //3
    gemm_fused<true, false><<<dim3(32, 2, 16), 256, SMEM_F>>>(
        wih, wil, x1, imgh, imgl, nullptr,
        512, 4096, 0, 512L * 4096, 256L * 4096, 0L);

    // 2) kv = w_txt @ x2 (fused); out kvh/kvl + transposed kvTh             //4
    gemm_fused<true, true><<<dim3(32, 2, 16), 256, SMEM_F>>>(
        wth, wtl, x2, kvh, kvl, kvTh,
        320, 4096, 256, 320L * 4096, 256L * 4096, 4096L * 256);

    // 3) logits partials (3-pass, split-K=8)                                //5
    gemm_mma<false, true, false, true><<<dim3(2, 2, 16 * NSPLIT), 256, SMEM_TOT>>>(
        imgh, imgl, kvh, kvl, part, nullptr, nullptr, nullptr, nullptr,
        NSP / NSPLIT, 4096, 4096, 256, 0,
        256L * 4096, 256L * 4096, 256L * 256, 0L, NSPLIT);

    // 4) softmax                                                            //6
    softmax_rows<<<BATCH * CCH, 256>>>(part, atth, attl);

    // 5) tT[n,c] = gamma*(attn @ kvT) + (imgh+imgl)  (2-pass, 4-stage)      //7
    gemm_mma<true, false, true, false><<<dim3(32, 2, 16), 256, SMEM_TOT>>>(
        atth, attl, kvTh, nullptr, nullptr, tTh, imgh, imgl, gamma,
        256, 256, 256, 4096, 256,
        256L * 256, 4096L * 256, 256L * 4096, 4096L * 256, 1);

    // 6) out = w_out @ tT  (2-pass, 4-stage)                                //8
    gemm_mma<false, true, false, false><<<dim3(32, 4, 16), 256, SMEM_TOT>>>(
        woh, wol, tTh, nullptr, out, nullptr, nullptr, nullptr, nullptr,
        256, 256, 256, 4096, 0,
        0L, 4096L * 256, 512L * 4096, 0L, 1);
}

// round 8
// speedup vs baseline: 3.4045x; 1.0065x over previous
#include <cuda_runtime.h>
#include <cuda_fp16.h>
#include <math.h>

using u32 = unsigned int;

// ===========================================================================
// Problem constants
// ===========================================================================
static const int BATCH  = 16;
static const int CCH    = 256;
static const int NSP    = 4096;
static const int NSPLIT = 8;     // split-K for logits GEMM

// ===========================================================================
// Device scratch (allocation-free)
// ===========================================================================
__device__ __half g_wih[256 * 512], g_wil[256 * 512];
__device__ __half g_wth[256 * 320], g_wtl[256 * 320];
__device__ __half g_woh[512 * 256], g_wol[512 * 256];
__device__ __half g_imgh[(size_t)BATCH * CCH * NSP];
__device__ __half g_imgl[(size_t)BATCH * CCH * NSP];
__device__ __half g_kvh [(size_t)BATCH * CCH * NSP];
__device__ __half g_kvl [(size_t)BATCH * CCH * NSP];
__device__ __half g_kvTh[(size_t)BATCH * NSP * CCH];
__device__ __half g_tTh [(size_t)BATCH * NSP * CCH];
__device__ float  g_part[(size_t)NSPLIT * BATCH * CCH * CCH];
__device__ __half g_atth[(size_t)BATCH * CCH * CCH];
__device__ __half g_attl[(size_t)BATCH * CCH * CCH];

// ===========================================================================
// PTX helpers (base-target ISA: cp.async / ldmatrix / mma.sync)
// ===========================================================================
__device__ __forceinline__ u32 smem_u32(const void* p) {
    u32 a;
    asm("{ .reg .u64 t; cvta.to.shared.u64 t, %1; cvt.u32.u64 %0, t; }"
        : "=r"(a) : "l"(p));
    return a;
}
__device__ __forceinline__ void cp16(u32 dst, const void* src) {
    asm volatile("cp.async.cg.shared.global [%0], [%1], 16;"
                 :: "r"(dst), "l"(src) : "memory");
}
__device__ __forceinline__ void cp_commit() {
    asm volatile("cp.async.commit_group;" ::: "memory");
}
template <int N>
__device__ __forceinline__ void cp_wait() {
    asm volatile("cp.async.wait_group %0;" :: "n"(N) : "memory");
}
#define LDMX4(d0, d1, d2, d3, addr) \
    asm volatile("ldmatrix.sync.aligned.m8n8.x4.shared.b16 {%0,%1,%2,%3},[%4];" \
                 : "=r"(d0), "=r"(d1), "=r"(d2), "=r"(d3) : "r"(addr))
#define MMA16816(c, a, b0, b1) \
    asm volatile("mma.sync.aligned.m16n8k16.row.col.f32.f16.f16.f32 " \
                 "{%0,%1,%2,%3},{%4,%5,%6,%7},{%8,%9},{%0,%1,%2,%3};" \
                 : "+f"((c)[0]), "+f"((c)[1]), "+f"((c)[2]), "+f"((c)[3]) \
                 : "r"((a)[0]), "r"((a)[1]), "r"((a)[2]), "r"((a)[3]), \
                   "r"(b0), "r"(b1))

__device__ __forceinline__ u32 pack2(__half a, __half b) {
    __half2 h = __halves2half2(a, b);
    return *(u32*)&h;
}

// ===========================================================================
// MERGED FUSED GEMM (stages 1+2 in one launch):
//   z <  16: imgh/imgl = split( w_img @ x1[z] ),      K=512
//   z >= 16: kvh/kvl   = split( w_txt @ x2[z-16] ),   K=320, + kvTh [n,m]
// X fp32 [K,N] transposed + hi/lo split on the fly (double staging buffers).
// 3-pass Markidis. Operand tiles pitch 80B (conflict-free, no XOR).
// ===========================================================================
static const int FT   = 10240;              // one 128x(64B@80B-pitch) tile
static const int FSTG = 8 * FT;             // 81920: staging area offset
static const int SMEM_F = FSTG + 2 * 16384; // 114688

__global__ __launch_bounds__(256, 2)
void gemm_fused(const __half* __restrict__ wih, const __half* __restrict__ wil,
                const float* __restrict__ x1,
                __half* __restrict__ imgh, __half* __restrict__ imgl,
                const __half* __restrict__ wth, const __half* __restrict__ wtl,
                const float* __restrict__ x2,
                __half* __restrict__ kvh, __half* __restrict__ kvl,
                __half* __restrict__ kvTh)
{
    extern __shared__ __align__(128) char sm[];
    const u32 smb = smem_u32(sm);
    const int tid = threadIdx.x;
    const int wid = tid >> 5;
    const int lid = tid & 31;
    const int wm  = wid >> 2;
    const int wn  = wid & 3;

    const int z   = blockIdx.z;
    const bool s2 = (z >= 16);
    const int b   = s2 ? (z - 16) : z;
    const int K   = s2 ? 320 : 512;
    const int m0  = blockIdx.y * 128;
    const int n0  = blockIdx.x * 128;
    const int ldC = 4096;
    const int ldT = 256;

    const __half* Ahm = (s2 ? wth : wih) + (size_t)m0 * K;
    const __half* Alm = (s2 ? wtl : wil) + (size_t)m0 * K;
    const float*  Xb  = (s2 ? x2 : x1) + (size_t)b * K * 4096;

    __half* CHhb = (s2 ? kvh : imgh) + (size_t)b * (256L * 4096);
    __half* CHlb = (s2 ? kvl : imgl) + (size_t)b * (256L * 4096);
    __half* CThb = s2 ? (kvTh + (size_t)b * (4096L * 256)) : nullptr;

    const int rAl = lid & 15;
    const int ksA = lid >> 4;
    const int rBl = ((lid >> 4) & 1) * 8 + (lid & 7);
    const int csB = (lid >> 3) & 1;

    auto cpA = [&](int chunk, int st) {
        const int kt = chunk * 32;
        #pragma unroll
        for (int t = 0; t < 2; t++) {
            const int task = tid + t * 256;
            const int r = task >> 2, c = task & 3;
            const u32 dst = smb + st * (4 * FT) + r * 80 + c * 16;
            cp16(dst,      Ahm + (size_t)r * K + kt + c * 8);
            cp16(dst + FT, Alm + (size_t)r * K + kt + c * 8);
        }
    };
    auto cpB = [&](int chunk) {
        const int kt = chunk * 32;
        const u32 dst0 = smb + FSTG + (chunk & 1) * 16384;
        #pragma unroll
        for (int t = 0; t < 4; t++) {
            const int task = tid + t * 256;
            const int kr = task >> 5, c16 = task & 31;
            cp16(dst0 + kr * 512 + c16 * 16,
                 Xb + (size_t)(kt + kr) * ldC + n0 + c16 * 4);
        }
    };
    auto convB = [&](int chunk) {
        const int st = chunk & 1;
        const float* stg = (const float*)(sm + FSTG + st * 16384);
        #pragma unroll
        for (int t = 0; t < 2; t++) {
            const int task = tid + t * 256;
            const int n = task & 127, ko = task >> 7;
            float f[8];
            #pragma unroll
            for (int i = 0; i < 8; i++)
                f[i] = stg[(ko * 8 + i) * 128 + n];
            __half h[8], l[8];
            #pragma unroll
            for (int i = 0; i < 8; i++) {
                h[i] = __float2half_rn(f[i]);
                l[i] = __float2half_rn(f[i] - __half2float(h[i]));
            }
            uint4 vh = make_uint4(pack2(h[0], h[1]), pack2(h[2], h[3]),
                                  pack2(h[4], h[5]), pack2(h[6], h[7]));
            uint4 vl = make_uint4(pack2(l[0], l[1]), pack2(l[2], l[3]),
                                  pack2(l[4], l[5]), pack2(l[6], l[7]));
            *(uint4*)(sm + st * (4 * FT) + 2 * FT + n * 80 + ko * 16) = vh;
            *(uint4*)(sm + st * (4 * FT) + 3 * FT + n * 80 + ko * 16) = vl;
        }
    };

    const int nC = K >> 5;

    float acc[4][4][4];
    #pragma unroll
    for (int i = 0; i < 4; i++)
        #pragma unroll
        for (int j = 0; j < 4; j++)
            #pragma unroll
            for (int q = 0; q < 4; q++) acc[i][j][q] = 0.0f;

    // prologue
    cpA(0, 0); cpB(0); cp_commit();
    cpA(1, 1); cpB(1); cp_commit();
    cp_wait<1>(); __syncthreads();
    convB(0);
    __syncthreads();

    for (int c = 0; c < nC; c++) {
        const int st = c & 1;
        const u32 tb = smb + st * (4 * FT);
        if (c + 2 < nC) { cpB(c + 2); cp_commit(); }   // early: staging c&1 free
        #pragma unroll
        for (int s16 = 0; s16 < 2; s16++) {
            u32 bh[8], bl[8];
            const u32 rb = (u32)((wn * 32 + rBl) * 80 + (2 * s16 + csB) * 16);
            LDMX4(bh[0], bh[1], bh[2], bh[3], tb + 2 * FT + rb);
            LDMX4(bh[4], bh[5], bh[6], bh[7], tb + 2 * FT + rb + 1280);
            LDMX4(bl[0], bl[1], bl[2], bl[3], tb + 3 * FT + rb);
            LDMX4(bl[4], bl[5], bl[6], bl[7], tb + 3 * FT + rb + 1280);
            #pragma unroll
            for (int mt = 0; mt < 4; mt++) {
                u32 ah[4], al[4];
                const u32 ra = (u32)((wm * 64 + mt * 16 + rAl) * 80 +
                                     (2 * s16 + ksA) * 16);
                LDMX4(ah[0], ah[1], ah[2], ah[3], tb + ra);
                LDMX4(al[0], al[1], al[2], al[3], tb + FT + ra);
                #pragma unroll
                for (int nt = 0; nt < 4; nt++) {
                    MMA16816(acc[mt][nt], ah, bh[2*nt], bh[2*nt+1]);
                    MMA16816(acc[mt][nt], ah, bl[2*nt], bl[2*nt+1]);
                    MMA16816(acc[mt][nt], al, bh[2*nt], bh[2*nt+1]);
                }
            }
        }
        if (c + 1 < nC) {
            if (c + 2 < nC) cp_wait<1>(); else cp_wait<0>();
            __syncthreads();
            convB(c + 1);
            __syncthreads();
            if (c + 2 < nC) { cpA(c + 2, st); cp_commit(); }
        }
    }

    // epilogue
    __syncthreads();
    __half* T = (__half*)sm;   // [128 n][136 m] transpose buffer
    #pragma unroll
    for (int mt = 0; mt < 4; mt++) {
        #pragma unroll
        for (int nt = 0; nt < 4; nt++) {
            const int nn = wn * 32 + nt * 8 + (lid & 3) * 2;
            #pragma unroll
            for (int h = 0; h < 2; h++) {
                const int ml = wm * 64 + mt * 16 + (lid >> 2) + h * 8;
                const int mm = m0 + ml;
                const float v0 = acc[mt][nt][2 * h];
                const float v1 = acc[mt][nt][2 * h + 1];
                const __half h0 = __float2half_rn(v0);
                const __half h1 = __float2half_rn(v1);
                const __half e0 = __float2half_rn(v0 - __half2float(h0));
                const __half e1 = __float2half_rn(v1 - __half2float(h1));
                *(__half2*)(CHhb + (size_t)mm * ldC + n0 + nn) =
                    __halves2half2(h0, h1);
                *(__half2*)(CHlb + (size_t)mm * ldC + n0 + nn) =
                    __halves2half2(e0, e1);
                if (s2) {
                    T[(size_t)nn * 136 + ml]       = h0;
                    T[(size_t)(nn + 1) * 136 + ml] = h1;
                }
            }
        }
    }
    if (s2) {
        __syncthreads();
        #pragma unroll
        for (int it = 0; it < 8; it++) {
            const int idx = it * 256 + tid;
            const int n  = idx >> 4;
            const int ck = idx & 15;
            const uint4 v = *(const uint4*)(T + (size_t)n * 136 + ck * 8);
            *(uint4*)(CThb + (size_t)(n0 + n) * ldT + m0 + ck * 8) = v;
        }
    }
}

// ===========================================================================
// PURE fp16 GEMM (stages 3,5,6).
// PB=true : 3-pass, 3 stages x 32KB.  PB=false: 2-pass, 4 stages x 24KB.
// ===========================================================================
static const int SMEM_TOT = 98304;

template <bool RESID, bool WN, bool WHT, bool PB>
__global__ __launch_bounds__(256, 2)
void gemm_mma(const __half* __restrict__ Ahg, const __half* __restrict__ Alg,
              const __half* __restrict__ Bhg, const __half* __restrict__ Blg,
              float* __restrict__ Cn, __half* __restrict__ CTh,
              const __half* __restrict__ Rhg, const __half* __restrict__ Rlg,
              const float* __restrict__ gamma,
              int K, int ldA, int ldB, int ldC, int ldT,
              long aBat, long bBat, long cBat, long tBat, int nsplit)
{
    constexpr int NST    = PB ? 3 : 4;
    constexpr int STRIDE = PB ? 32768 : 24576;

    extern __shared__ __align__(128) char sm[];
    const u32 smb = smem_u32(sm);
    const int tid = threadIdx.x;
    const int wid = tid >> 5;
    const int lid = tid & 31;
    const int wm  = wid >> 2;
    const int wn  = wid & 3;

    const int z = blockIdx.z;
    const int b = z / nsplit;
    const int s = z - b * nsplit;
    const int nbat = gridDim.z / nsplit;

    const __half* Ah = Ahg + (size_t)b * aBat + (size_t)s * K;
    const __half* Al = Alg + (size_t)b * aBat + (size_t)s * K;
    const __half* Bh = Bhg + (size_t)b * bBat + (size_t)s * K;
    const __half* Bl = PB ? (Blg + (size_t)b * bBat + (size_t)s * K) : nullptr;

    const size_t ob = (size_t)s * nbat + b;
    float*  Cb   = WN  ? (Cn  + ob * cBat) : nullptr;
    __half* CThb = WHT ? (CTh + ob * tBat) : nullptr;
    const __half* Rh = RESID ? (Rhg + (size_t)b * cBat) : nullptr;
    const __half* Rl = RESID ? (Rlg + (size_t)b * cBat) : nullptr;

    const int m0 = blockIdx.y * 128;
    const int n0 = blockIdx.x * 128;

    const __half* Ahm = Ah + (size_t)m0 * ldA;
    const __half* Alm = Al + (size_t)m0 * ldA;
    const __half* Bhn = Bh + (size_t)n0 * ldB;
    const __half* Bln = PB ? (Bl + (size_t)n0 * ldB) : nullptr;

    const int rAl = lid & 15;
    const int ksA = lid >> 4;
    const int xA  = (rAl >> 1) & 3;
    const int rBl = ((lid >> 4) & 1) * 8 + (lid & 7);
    const int csB = (lid >> 3) & 1;
    const int xB  = (rBl >> 1) & 3;

    auto ldStage = [&](int chunk, int stg) {
        const u32 sb = smb + stg * STRIDE;
        const int kt = chunk * 32;
        #pragma unroll
        for (int p = 0; p < 2; p++) {
            const int idx = tid + p * 256;
            const int r = idx >> 2;
            const int c = idx & 3;
            const u32 soff = r * 64 + ((c ^ ((r >> 1) & 3)) << 4);
            const size_t ga = (size_t)r * ldA + kt + c * 8;
            const size_t gb = (size_t)r * ldB + kt + c * 8;
            cp16(sb + soff,          Ahm + ga);
            cp16(sb + 8192 + soff,   Alm + ga);
            cp16(sb + 16384 + soff,  Bhn + gb);
            if constexpr (PB) cp16(sb + 24576 + soff, Bln + gb);
        }
    };

    const int nC = K >> 5;

    float acc[4][4][4];
    #pragma unroll
    for (int i = 0; i < 4; i++)
        #pragma unroll
        for (int j = 0; j < 4; j++)
            #pragma unroll
            for (int q = 0; q < 4; q++) acc[i][j][q] = 0.0f;

    #pragma unroll
    for (int p = 0; p < NST - 1; p++) { ldStage(p, p); cp_commit(); }

    for (int c = 0; c < nC; c++) {
        const int rem = nC - 1 - c;
        if constexpr (PB) {
            if (rem >= 1) cp_wait<1>(); else cp_wait<0>();
        } else {
            if (rem >= 2) cp_wait<2>();
            else if (rem == 1) cp_wait<1>();
            else cp_wait<0>();
        }
        __syncthreads();
        if (c + NST - 1 < nC) { ldStage(c + NST - 1, (c + NST - 1) % NST); cp_commit(); }

        const u32 tb = smb + (c % NST) * STRIDE;
        #pragma unroll
        for (int s16 = 0; s16 < 2; s16++) {
            u32 bh[8], bl[8];
            const u32 rb = (u32)((wn * 32 + rBl) * 64 +
                                 (((2 * s16 + csB) ^ xB) << 4));
            LDMX4(bh[0], bh[1], bh[2], bh[3], tb + 16384 + rb);
            LDMX4(bh[4], bh[5], bh[6], bh[7], tb + 16384 + rb + 1024);
            if constexpr (PB) {
                LDMX4(bl[0], bl[1], bl[2], bl[3], tb + 24576 + rb);
                LDMX4(bl[4], bl[5], bl[6], bl[7], tb + 24576 + rb + 1024);
            }
            #pragma unroll
            for (int mt = 0; mt < 4; mt++) {
                u32 ah[4], al[4];
                const u32 ra = (u32)((wm * 64 + mt * 16 + rAl) * 64 +
                                     (((2 * s16 + ksA) ^ xA) << 4));
                LDMX4(ah[0], ah[1], ah[2], ah[3], tb + ra);
                LDMX4(al[0], al[1], al[2], al[3], tb + 8192 + ra);
                #pragma unroll
                for (int nt = 0; nt < 4; nt++) {
                    MMA16816(acc[mt][nt], ah, bh[2*nt], bh[2*nt+1]);
                    if constexpr (PB)
                        MMA16816(acc[mt][nt], ah, bl[2*nt], bl[2*nt+1]);
                    MMA16816(acc[mt][nt], al, bh[2*nt], bh[2*nt+1]);
                }
            }
        }
    }

    // epilogue
    if (WHT) __syncthreads();
    __half* T = (__half*)sm;

    const float gm = RESID ? gamma[0] : 0.0f;
    #pragma unroll
    for (int mt = 0; mt < 4; mt++) {
        #pragma unroll
        for (int nt = 0; nt < 4; nt++) {
            const int nn = wn * 32 + nt * 8 + (lid & 3) * 2;
            #pragma unroll
            for (int h = 0; h < 2; h++) {
                const int ml = wm * 64 + mt * 16 + (lid >> 2) + h * 8;
                const int mm = m0 + ml;
                float v0 = acc[mt][nt][2 * h];
                float v1 = acc[mt][nt][2 * h + 1];
                if (RESID) {
                    const size_t off = (size_t)mm * ldC + n0 + nn;
                    const __half2 rh = *(const __half2*)(Rh + off);
                    const __half2 rl = *(const __half2*)(Rl + off);
                    v0 = gm * v0 + __low2float(rh)  + __low2float(rl);
                    v1 = gm * v1 + __high2float(rh) + __high2float(rl);
                }
                if (WN)
                    *(float2*)(Cb + (size_t)mm * ldC + n0 + nn) =
                        make_float2(v0, v1);
                if (WHT) {
                    T[(size_t)nn * 136 + ml]       = __float2half_rn(v0);
                    T[(size_t)(nn + 1) * 136 + ml] = __float2half_rn(v1);
                }
            }
        }
    }

    if (WHT) {
        __syncthreads();
        #pragma unroll
        for (int it = 0; it < 8; it++) {
            const int idx = it * 256 + tid;
            const int n  = idx >> 4;
            const int ck = idx & 15;
            const uint4 v = *(const uint4*)(T + (size_t)n * 136 + ck * 8);
            *(uint4*)(CThb + (size_t)(n0 + n) * ldT + m0 + ck * 8) = v;
        }
    }
}

// ===========================================================================
// Merged weight split: three fp32->fp16 hi/lo splits in one launch.
// Segments: [0, 131072) w_img | [131072, 213kB...) w_txt | then w_out.
// ===========================================================================
static const int NW1 = 256 * 512;            // 131072
static const int NW2 = 256 * 320;            // 81920
static const int NW3 = 512 * 256;            // 131072

__global__ __launch_bounds__(256)
void split_w3(const float* __restrict__ w1, const float* __restrict__ w2,
              const float* __restrict__ w3,
              __half* __restrict__ o1h, __half* __restrict__ o1l,
              __half* __restrict__ o2h, __half* __restrict__ o2l,
              __half* __restrict__ o3h, __half* __restrict__ o3l)
{
    int i = blockIdx.x * 256 + threadIdx.x;
    const float* in; __half *oh, *ol;
    if (i < NW1)                  { in = w1; oh = o1h; ol = o1l; }
    else if (i < NW1 + NW2)       { i -= NW1; in = w2; oh = o2h; ol = o2l; }
    else if (i < NW1 + NW2 + NW3) { i -= NW1 + NW2; in = w3; oh = o3h; ol = o3l; }
    else return;
    const float v = in[i];
    const __half hh = __float2half_rn(v);
    oh[i] = hh;
    ol[i] = __float2half_rn(v - __half2float(hh));
}

// ===========================================================================
// Softmax over rows of 256 (sums NSPLIT split-K partials), emits hi/lo fp16.
// ===========================================================================
__global__ __launch_bounds__(256)
void softmax_rows(const float* __restrict__ P, __half* __restrict__ Ah,
                  __half* __restrict__ Al)
{
    const size_t RS = (size_t)BATCH * CCH * CCH;
    const int row = blockIdx.x;
    const int tid = threadIdx.x;
    const size_t base = (size_t)row * CCH + tid;
    float x = 0.0f;
    #pragma unroll
    for (int s = 0; s < NSPLIT; s++) x += P[s * RS + base];

    __shared__ float red[256];
    red[tid] = x;
    __syncthreads();
    for (int o = 128; o > 0; o >>= 1) {
        if (tid < o) red[tid] = fmaxf(red[tid], red[tid + o]);
        __syncthreads();
    }
    const float mx = red[0];
    __syncthreads();
    const float e = expf(x - mx);
    red[tid] = e;
    __syncthreads();
    for (int o = 128; o > 0; o >>= 1) {
        if (tid < o) red[tid] += red[tid + o];
        __syncthreads();
    }
    const float p = e / red[0];
    const __half hh = __float2half_rn(p);
    Ah[base] = hh;
    Al[base] = __float2half_rn(p - __half2float(hh));
}

// ===========================================================================
// Launch
// ===========================================================================
extern "C" void kernel_launch(void* const* d_in, const int* in_sizes, int n_in,
                              void* d_out, int out_size)
{
    const float* x1    = (const float*)d_in[0];
    const float* x2    = (const float*)d_in[1];
    const float* w_img = (const float*)d_in[2];
    const float* w_txt = (const float*)d_in[3];
    const float* w_out = (const float*)d_in[4];
    const float* gamma = (const float*)d_in[5];
    float* out = (float*)d_out;

    __half *wih, *wil, *wth, *wtl, *woh, *wol;
    __half *imgh, *imgl, *kvh, *kvl, *kvTh, *tTh, *atth, *attl;
    float *part;
    cudaGetSymbolAddress((void**)&wih,  g_wih);
    cudaGetSymbolAddress((void**)&wil,  g_wil);
    cudaGetSymbolAddress((void**)&wth,  g_wth);
    cudaGetSymbolAddress((void**)&wtl,  g_wtl);
    cudaGetSymbolAddress((void**)&woh,  g_woh);
    cudaGetSymbolAddress((void**)&wol,  g_wol);
    cudaGetSymbolAddress((void**)&imgh, g_imgh);
    cudaGetSymbolAddress((void**)&imgl, g_imgl);
    cudaGetSymbolAddress((void**)&kvh,  g_kvh);
    cudaGetSymbolAddress((void**)&kvl,  g_kvl);
    cudaGetSymbolAddress((void**)&kvTh, g_kvTh);
    cudaGetSymbolAddress((void**)&tTh,  g_tTh);
    cudaGetSymbolAddress((void**)&part, g_part);
    cudaGetSymbolAddress((void**)&atth, g_atth);
    cudaGetSymbolAddress((void**)&attl, g_attl);

    cudaFuncSetAttribute(gemm_fused,
                         cudaFuncAttributeMaxDynamicSharedMemorySize, SMEM_F);
    cudaFuncSetAttribute(gemm_mma<false, true,  false, true >,
                         cudaFuncAttributeMaxDynamicSharedMemorySize, SMEM_TOT);
    cudaFuncSetAttribute(gemm_mma<true,  false, true,  false>,
                         cudaFuncAttributeMaxDynamicSharedMemorySize, SMEM_TOT);
    cudaFuncSetAttribute(gemm_mma<false, true,  false, false>,
                         cudaFuncAttributeMaxDynamicSharedMemorySize, SMEM_TOT);

    // 0) all weight splits in one launch                                    //0
    split_w3<<<(NW1 + NW2 + NW3 + 255) / 256, 256>>>(
        w_img, w_txt, w_out, wih, wil, wth, wtl, woh, wol);

    // 1+2) img & kv projections, fused transpose+split, one launch          //1
    gemm_fused<<<dim3(32, 2, 32), 256, SMEM_F>>>(
        wih, wil, x1, imgh, imgl,
        wth, wtl, x2, kvh, kvl, kvTh);

    // 3) logits partials (3-pass, split-K=8)                                //2
    gemm_mma<false, true, false, true><<<dim3(2, 2, 16 * NSPLIT), 256, SMEM_TOT>>>(
        imgh, imgl, kvh, kvl, part, nullptr, nullptr, nullptr, nullptr,
        NSP / NSPLIT, 4096, 4096, 256, 0,
        256L * 4096, 256L * 4096, 256L * 256, 0L, NSPLIT);

    // 4) softmax                                                            //3
    softmax_rows<<<BATCH * CCH, 256>>>(part, atth, attl);

    // 5) tT[n,c] = gamma*(attn @ kvT) + (imgh+imgl)  (2-pass, 4-stage)      //4
    gemm_mma<true, false, true, false><<<dim3(32, 2, 16), 256, SMEM_TOT>>>(
        atth, attl, kvTh, nullptr, nullptr, tTh, imgh, imgl, gamma,
        256, 256, 256, 4096, 256,
        256L * 256, 4096L * 256, 256L * 4096, 4096L * 256, 1);

    // 6) out = w_out @ tT  (2-pass, 4-stage)                                //5
    gemm_mma<false, true, false, false><<<dim3(32, 4, 16), 256, SMEM_TOT>>>(
        woh, wol, tTh, nullptr, out, nullptr, nullptr, nullptr, nullptr,
        256, 256, 256, 4096, 0,
        0L, 4096L * 256, 512L * 4096, 0L, 1);
}

// round 9
// speedup vs baseline: 3.7276x; 1.0949x over previous
#include <cuda_runtime.h>
#include <cuda_fp16.h>
#include <math.h>

using u32 = unsigned int;

// ===========================================================================
// Problem constants
// ===========================================================================
static const int BATCH  = 16;
static const int CCH    = 256;
static const int NSP    = 4096;
static const int NSPLIT = 8;     // split-K for logits GEMM

// ===========================================================================
// Device scratch (allocation-free)
// ===========================================================================
__device__ __half g_wih[256 * 512], g_wil[256 * 512];
__device__ __half g_wth[256 * 320], g_wtl[256 * 320];
__device__ __half g_woh[512 * 256], g_wol[512 * 256];
__device__ __half g_imgh[(size_t)BATCH * CCH * NSP];
__device__ __half g_imgl[(size_t)BATCH * CCH * NSP];
__device__ __half g_kvh [(size_t)BATCH * CCH * NSP];
__device__ __half g_kvl [(size_t)BATCH * CCH * NSP];
__device__ __half g_kvTh[(size_t)BATCH * NSP * CCH];
__device__ __half g_tTh [(size_t)BATCH * NSP * CCH];
__device__ float  g_part[(size_t)NSPLIT * BATCH * CCH * CCH];
__device__ __half g_atth[(size_t)BATCH * CCH * CCH];

// ===========================================================================
// PTX helpers (base-target ISA: cp.async / ldmatrix / mma.sync)
// ===========================================================================
__device__ __forceinline__ u32 smem_u32(const void* p) {
    u32 a;
    asm("{ .reg .u64 t; cvta.to.shared.u64 t, %1; cvt.u32.u64 %0, t; }"
        : "=r"(a) : "l"(p));
    return a;
}
__device__ __forceinline__ void cp16(u32 dst, const void* src) {
    asm volatile("cp.async.cg.shared.global [%0], [%1], 16;"
                 :: "r"(dst), "l"(src) : "memory");
}
__device__ __forceinline__ void cp_commit() {
    asm volatile("cp.async.commit_group;" ::: "memory");
}
template <int N>
__device__ __forceinline__ void cp_wait() {
    asm volatile("cp.async.wait_group %0;" :: "n"(N) : "memory");
}
#define LDMX4(d0, d1, d2, d3, addr) \
    asm volatile("ldmatrix.sync.aligned.m8n8.x4.shared.b16 {%0,%1,%2,%3},[%4];" \
                 : "=r"(d0), "=r"(d1), "=r"(d2), "=r"(d3) : "r"(addr))
#define MMA16816(c, a, b0, b1) \
    asm volatile("mma.sync.aligned.m16n8k16.row.col.f32.f16.f16.f32 " \
                 "{%0,%1,%2,%3},{%4,%5,%6,%7},{%8,%9},{%0,%1,%2,%3};" \
                 : "+f"((c)[0]), "+f"((c)[1]), "+f"((c)[2]), "+f"((c)[3]) \
                 : "r"((a)[0]), "r"((a)[1]), "r"((a)[2]), "r"((a)[3]), \
                   "r"(b0), "r"(b1))

__device__ __forceinline__ u32 pack2(__half a, __half b) {
    __half2 h = __halves2half2(a, b);
    return *(u32*)&h;
}

// ===========================================================================
// MERGED FUSED GEMM (stages 1+2 in one launch):
//   z <  16: imgh/imgl = split( w_img @ x1[z] ),      K=512
//   z >= 16: kvh/kvl   = split( w_txt @ x2[z-16] ),   K=320, + kvTh [n,m]
// X fp32 [K,N] transposed + hi/lo split on the fly (double staging buffers).
// 3-pass Markidis. Operand tiles pitch 80B (conflict-free, no XOR).
// ===========================================================================
static const int FT   = 10240;              // one 128x(64B@80B-pitch) tile
static const int FSTG = 8 * FT;             // 81920: staging area offset
static const int SMEM_F = FSTG + 2 * 16384; // 114688

__global__ __launch_bounds__(256, 2)
void gemm_fused(const __half* __restrict__ wih, const __half* __restrict__ wil,
                const float* __restrict__ x1,
                __half* __restrict__ imgh, __half* __restrict__ imgl,
                const __half* __restrict__ wth, const __half* __restrict__ wtl,
                const float* __restrict__ x2,
                __half* __restrict__ kvh, __half* __restrict__ kvl,
                __half* __restrict__ kvTh)
{
    extern __shared__ __align__(128) char sm[];
    const u32 smb = smem_u32(sm);
    const int tid = threadIdx.x;
    const int wid = tid >> 5;
    const int lid = tid & 31;
    const int wm  = wid >> 2;
    const int wn  = wid & 3;

    const int z   = blockIdx.z;
    const bool s2 = (z >= 16);
    const int b   = s2 ? (z - 16) : z;
    const int K   = s2 ? 320 : 512;
    const int m0  = blockIdx.y * 128;
    const int n0  = blockIdx.x * 128;
    const int ldC = 4096;
    const int ldT = 256;

    const __half* Ahm = (s2 ? wth : wih) + (size_t)m0 * K;
    const __half* Alm = (s2 ? wtl : wil) + (size_t)m0 * K;
    const float*  Xb  = (s2 ? x2 : x1) + (size_t)b * K * 4096;

    __half* CHhb = (s2 ? kvh : imgh) + (size_t)b * (256L * 4096);
    __half* CHlb = (s2 ? kvl : imgl) + (size_t)b * (256L * 4096);
    __half* CThb = s2 ? (kvTh + (size_t)b * (4096L * 256)) : nullptr;

    const int rAl = lid & 15;
    const int ksA = lid >> 4;
    const int rBl = ((lid >> 4) & 1) * 8 + (lid & 7);
    const int csB = (lid >> 3) & 1;

    auto cpA = [&](int chunk, int st) {
        const int kt = chunk * 32;
        #pragma unroll
        for (int t = 0; t < 2; t++) {
            const int task = tid + t * 256;
            const int r = task >> 2, c = task & 3;
            const u32 dst = smb + st * (4 * FT) + r * 80 + c * 16;
            cp16(dst,      Ahm + (size_t)r * K + kt + c * 8);
            cp16(dst + FT, Alm + (size_t)r * K + kt + c * 8);
        }
    };
    auto cpB = [&](int chunk) {
        const int kt = chunk * 32;
        const u32 dst0 = smb + FSTG + (chunk & 1) * 16384;
        #pragma unroll
        for (int t = 0; t < 4; t++) {
            const int task = tid + t * 256;
            const int kr = task >> 5, c16 = task & 31;
            cp16(dst0 + kr * 512 + c16 * 16,
                 Xb + (size_t)(kt + kr) * ldC + n0 + c16 * 4);
        }
    };
    auto convB = [&](int chunk) {
        const int st = chunk & 1;
        const float* stg = (const float*)(sm + FSTG + st * 16384);
        #pragma unroll
        for (int t = 0; t < 2; t++) {
            const int task = tid + t * 256;
            const int n = task & 127, ko = task >> 7;
            float f[8];
            #pragma unroll
            for (int i = 0; i < 8; i++)
                f[i] = stg[(ko * 8 + i) * 128 + n];
            __half h[8], l[8];
            #pragma unroll
            for (int i = 0; i < 8; i++) {
                h[i] = __float2half_rn(f[i]);
                l[i] = __float2half_rn(f[i] - __half2float(h[i]));
            }
            uint4 vh = make_uint4(pack2(h[0], h[1]), pack2(h[2], h[3]),
                                  pack2(h[4], h[5]), pack2(h[6], h[7]));
            uint4 vl = make_uint4(pack2(l[0], l[1]), pack2(l[2], l[3]),
                                  pack2(l[4], l[5]), pack2(l[6], l[7]));
            *(uint4*)(sm + st * (4 * FT) + 2 * FT + n * 80 + ko * 16) = vh;
            *(uint4*)(sm + st * (4 * FT) + 3 * FT + n * 80 + ko * 16) = vl;
        }
    };

    const int nC = K >> 5;

    float acc[4][4][4];
    #pragma unroll
    for (int i = 0; i < 4; i++)
        #pragma unroll
        for (int j = 0; j < 4; j++)
            #pragma unroll
            for (int q = 0; q < 4; q++) acc[i][j][q] = 0.0f;

    // prologue
    cpA(0, 0); cpB(0); cp_commit();
    cpA(1, 1); cpB(1); cp_commit();
    cp_wait<1>(); __syncthreads();
    convB(0);
    __syncthreads();

    for (int c = 0; c < nC; c++) {
        const int st = c & 1;
        const u32 tb = smb + st * (4 * FT);
        if (c + 2 < nC) { cpB(c + 2); cp_commit(); }   // early: staging c&1 free
        #pragma unroll
        for (int s16 = 0; s16 < 2; s16++) {
            u32 bh[8], bl[8];
            const u32 rb = (u32)((wn * 32 + rBl) * 80 + (2 * s16 + csB) * 16);
            LDMX4(bh[0], bh[1], bh[2], bh[3], tb + 2 * FT + rb);
            LDMX4(bh[4], bh[5], bh[6], bh[7], tb + 2 * FT + rb + 1280);
            LDMX4(bl[0], bl[1], bl[2], bl[3], tb + 3 * FT + rb);
            LDMX4(bl[4], bl[5], bl[6], bl[7], tb + 3 * FT + rb + 1280);
            #pragma unroll
            for (int mt = 0; mt < 4; mt++) {
                u32 ah[4], al[4];
                const u32 ra = (u32)((wm * 64 + mt * 16 + rAl) * 80 +
                                     (2 * s16 + ksA) * 16);
                LDMX4(ah[0], ah[1], ah[2], ah[3], tb + ra);
                LDMX4(al[0], al[1], al[2], al[3], tb + FT + ra);
                #pragma unroll
                for (int nt = 0; nt < 4; nt++) {
                    MMA16816(acc[mt][nt], ah, bh[2*nt], bh[2*nt+1]);
                    MMA16816(acc[mt][nt], ah, bl[2*nt], bl[2*nt+1]);
                    MMA16816(acc[mt][nt], al, bh[2*nt], bh[2*nt+1]);
                }
            }
        }
        if (c + 1 < nC) {
            if (c + 2 < nC) cp_wait<1>(); else cp_wait<0>();
            __syncthreads();
            convB(c + 1);
            __syncthreads();
            if (c + 2 < nC) { cpA(c + 2, st); cp_commit(); }
        }
    }

    // epilogue
    __syncthreads();
    __half* T = (__half*)sm;   // [128 n][136 m] transpose buffer
    #pragma unroll
    for (int mt = 0; mt < 4; mt++) {
        #pragma unroll
        for (int nt = 0; nt < 4; nt++) {
            const int nn = wn * 32 + nt * 8 + (lid & 3) * 2;
            #pragma unroll
            for (int h = 0; h < 2; h++) {
                const int ml = wm * 64 + mt * 16 + (lid >> 2) + h * 8;
                const int mm = m0 + ml;
                const float v0 = acc[mt][nt][2 * h];
                const float v1 = acc[mt][nt][2 * h + 1];
                const __half h0 = __float2half_rn(v0);
                const __half h1 = __float2half_rn(v1);
                const __half e0 = __float2half_rn(v0 - __half2float(h0));
                const __half e1 = __float2half_rn(v1 - __half2float(h1));
                *(__half2*)(CHhb + (size_t)mm * ldC + n0 + nn) =
                    __halves2half2(h0, h1);
                *(__half2*)(CHlb + (size_t)mm * ldC + n0 + nn) =
                    __halves2half2(e0, e1);
                if (s2) {
                    T[(size_t)nn * 136 + ml]       = h0;
                    T[(size_t)(nn + 1) * 136 + ml] = h1;
                }
            }
        }
    }
    if (s2) {
        __syncthreads();
        #pragma unroll
        for (int it = 0; it < 8; it++) {
            const int idx = it * 256 + tid;
            const int n  = idx >> 4;
            const int ck = idx & 15;
            const uint4 v = *(const uint4*)(T + (size_t)n * 136 + ck * 8);
            *(uint4*)(CThb + (size_t)(n0 + n) * ldT + m0 + ck * 8) = v;
        }
    }
}

// ===========================================================================
// PURE fp16 GEMM (stages 3,5,6), NPASS ∈ {1,2,3}:
//   NPASS=3: AhBh + AhBl + AlBh   (stage 32KB, 3-stage ring)
//   NPASS=2: AhBh + AlBh          (stage 24KB, 4-stage ring)
//   NPASS=1: AhBh                 (stage 16KB, 6-stage ring)
// ===========================================================================
static const int SMEM_TOT = 98304;

template <bool RESID, bool WN, bool WHT, int NPASS>
__global__ __launch_bounds__(256, 2)
void gemm_mma(const __half* __restrict__ Ahg, const __half* __restrict__ Alg,
              const __half* __restrict__ Bhg, const __half* __restrict__ Blg,
              float* __restrict__ Cn, __half* __restrict__ CTh,
              const __half* __restrict__ Rhg, const __half* __restrict__ Rlg,
              const float* __restrict__ gamma,
              int K, int ldA, int ldB, int ldC, int ldT,
              long aBat, long bBat, long cBat, long tBat, int nsplit)
{
    constexpr int NTILE  = 2 + (NPASS >= 2 ? 1 : 0) + (NPASS >= 3 ? 1 : 0);
    constexpr int STRIDE = NTILE * 8192;
    constexpr int NST    = (NPASS == 1) ? 6 : (NPASS == 2 ? 4 : 3);
    constexpr int OB     = (NPASS >= 2) ? 16384 : 8192;  // Bh tile offset

    extern __shared__ __align__(128) char sm[];
    const u32 smb = smem_u32(sm);
    const int tid = threadIdx.x;
    const int wid = tid >> 5;
    const int lid = tid & 31;
    const int wm  = wid >> 2;
    const int wn  = wid & 3;

    const int z = blockIdx.z;
    const int b = z / nsplit;
    const int s = z - b * nsplit;
    const int nbat = gridDim.z / nsplit;

    const __half* Ah = Ahg + (size_t)b * aBat + (size_t)s * K;
    const __half* Al = (NPASS >= 2) ? (Alg + (size_t)b * aBat + (size_t)s * K)
                                    : nullptr;
    const __half* Bh = Bhg + (size_t)b * bBat + (size_t)s * K;
    const __half* Bl = (NPASS >= 3) ? (Blg + (size_t)b * bBat + (size_t)s * K)
                                    : nullptr;

    const size_t ob = (size_t)s * nbat + b;
    float*  Cb   = WN  ? (Cn  + ob * cBat) : nullptr;
    __half* CThb = WHT ? (CTh + ob * tBat) : nullptr;
    const __half* Rh = RESID ? (Rhg + (size_t)b * cBat) : nullptr;
    const __half* Rl = RESID ? (Rlg + (size_t)b * cBat) : nullptr;

    const int m0 = blockIdx.y * 128;
    const int n0 = blockIdx.x * 128;

    const __half* Ahm = Ah + (size_t)m0 * ldA;
    const __half* Alm = (NPASS >= 2) ? (Al + (size_t)m0 * ldA) : nullptr;
    const __half* Bhn = Bh + (size_t)n0 * ldB;
    const __half* Bln = (NPASS >= 3) ? (Bl + (size_t)n0 * ldB) : nullptr;

    const int rAl = lid & 15;
    const int ksA = lid >> 4;
    const int xA  = (rAl >> 1) & 3;
    const int rBl = ((lid >> 4) & 1) * 8 + (lid & 7);
    const int csB = (lid >> 3) & 1;
    const int xB  = (rBl >> 1) & 3;

    auto ldStage = [&](int chunk, int stg) {
        const u32 sb = smb + stg * STRIDE;
        const int kt = chunk * 32;
        #pragma unroll
        for (int p = 0; p < 2; p++) {
            const int idx = tid + p * 256;
            const int r = idx >> 2;
            const int c = idx & 3;
            const u32 soff = r * 64 + ((c ^ ((r >> 1) & 3)) << 4);
            const size_t ga = (size_t)r * ldA + kt + c * 8;
            const size_t gb = (size_t)r * ldB + kt + c * 8;
            cp16(sb + soff, Ahm + ga);
            if constexpr (NPASS >= 2) cp16(sb + 8192 + soff, Alm + ga);
            cp16(sb + OB + soff, Bhn + gb);
            if constexpr (NPASS >= 3) cp16(sb + 24576 + soff, Bln + gb);
        }
    };

    const int nC = K >> 5;

    float acc[4][4][4];
    #pragma unroll
    for (int i = 0; i < 4; i++)
        #pragma unroll
        for (int j = 0; j < 4; j++)
            #pragma unroll
            for (int q = 0; q < 4; q++) acc[i][j][q] = 0.0f;

    #pragma unroll
    for (int p = 0; p < NST - 1; p++)
        if (p < nC) { ldStage(p, p); cp_commit(); } else { cp_commit(); }

    for (int c = 0; c < nC; c++) {
        const int rem = nC - 1 - c;
        int tgt = NST - 2; if (rem < tgt) tgt = rem;
        switch (tgt) {
            case 0: cp_wait<0>(); break;
            case 1: cp_wait<1>(); break;
            case 2: cp_wait<2>(); break;
            case 3: cp_wait<3>(); break;
            default: cp_wait<4>(); break;
        }
        __syncthreads();
        if (c + NST - 1 < nC) { ldStage(c + NST - 1, (c + NST - 1) % NST); cp_commit(); }

        const u32 tb = smb + (c % NST) * STRIDE;
        #pragma unroll
        for (int s16 = 0; s16 < 2; s16++) {
            u32 bh[8], bl[8];
            const u32 rb = (u32)((wn * 32 + rBl) * 64 +
                                 (((2 * s16 + csB) ^ xB) << 4));
            LDMX4(bh[0], bh[1], bh[2], bh[3], tb + OB + rb);
            LDMX4(bh[4], bh[5], bh[6], bh[7], tb + OB + rb + 1024);
            if constexpr (NPASS >= 3) {
                LDMX4(bl[0], bl[1], bl[2], bl[3], tb + 24576 + rb);
                LDMX4(bl[4], bl[5], bl[6], bl[7], tb + 24576 + rb + 1024);
            }
            #pragma unroll
            for (int mt = 0; mt < 4; mt++) {
                u32 ah[4], al[4];
                const u32 ra = (u32)((wm * 64 + mt * 16 + rAl) * 64 +
                                     (((2 * s16 + ksA) ^ xA) << 4));
                LDMX4(ah[0], ah[1], ah[2], ah[3], tb + ra);
                if constexpr (NPASS >= 2)
                    LDMX4(al[0], al[1], al[2], al[3], tb + 8192 + ra);
                #pragma unroll
                for (int nt = 0; nt < 4; nt++) {
                    MMA16816(acc[mt][nt], ah, bh[2*nt], bh[2*nt+1]);
                    if constexpr (NPASS >= 3)
                        MMA16816(acc[mt][nt], ah, bl[2*nt], bl[2*nt+1]);
                    if constexpr (NPASS >= 2)
                        MMA16816(acc[mt][nt], al, bh[2*nt], bh[2*nt+1]);
                }
            }
        }
    }

    // epilogue
    if (WHT) __syncthreads();
    __half* T = (__half*)sm;

    const float gm = RESID ? gamma[0] : 0.0f;
    #pragma unroll
    for (int mt = 0; mt < 4; mt++) {
        #pragma unroll
        for (int nt = 0; nt < 4; nt++) {
            const int nn = wn * 32 + nt * 8 + (lid & 3) * 2;
            #pragma unroll
            for (int h = 0; h < 2; h++) {
                const int ml = wm * 64 + mt * 16 + (lid >> 2) + h * 8;
                const int mm = m0 + ml;
                float v0 = acc[mt][nt][2 * h];
                float v1 = acc[mt][nt][2 * h + 1];
                if (RESID) {
                    const size_t off = (size_t)mm * ldC + n0 + nn;
                    const __half2 rh = *(const __half2*)(Rh + off);
                    const __half2 rl = *(const __half2*)(Rl + off);
                    v0 = gm * v0 + __low2float(rh)  + __low2float(rl);
                    v1 = gm * v1 + __high2float(rh) + __high2float(rl);
                }
                if (WN)
                    *(float2*)(Cb + (size_t)mm * ldC + n0 + nn) =
                        make_float2(v0, v1);
                if (WHT) {
                    T[(size_t)nn * 136 + ml]       = __float2half_rn(v0);
                    T[(size_t)(nn + 1) * 136 + ml] = __float2half_rn(v1);
                }
            }
        }
    }

    if (WHT) {
        __syncthreads();
        #pragma unroll
        for (int it = 0; it < 8; it++) {
            const int idx = it * 256 + tid;
            const int n  = idx >> 4;
            const int ck = idx & 15;
            const uint4 v = *(const uint4*)(T + (size_t)n * 136 + ck * 8);
            *(uint4*)(CThb + (size_t)(n0 + n) * ldT + m0 + ck * 8) = v;
        }
    }
}

// ===========================================================================
// Merged weight split: three fp32->fp16 hi/lo splits in one launch.
// ===========================================================================
static const int NW1 = 256 * 512;
static const int NW2 = 256 * 320;
static const int NW3 = 512 * 256;

__global__ __launch_bounds__(256)
void split_w3(const float* __restrict__ w1, const float* __restrict__ w2,
              const float* __restrict__ w3,
              __half* __restrict__ o1h, __half* __restrict__ o1l,
              __half* __restrict__ o2h, __half* __restrict__ o2l,
              __half* __restrict__ o3h, __half* __restrict__ o3l)
{
    int i = blockIdx.x * 256 + threadIdx.x;
    const float* in; __half *oh, *ol;
    if (i < NW1)                  { in = w1; oh = o1h; ol = o1l; }
    else if (i < NW1 + NW2)       { i -= NW1; in = w2; oh = o2h; ol = o2l; }
    else if (i < NW1 + NW2 + NW3) { i -= NW1 + NW2; in = w3; oh = o3h; ol = o3l; }
    else return;
    const float v = in[i];
    const __half hh = __float2half_rn(v);
    oh[i] = hh;
    ol[i] = __float2half_rn(v - __half2float(hh));
}

// ===========================================================================
// Softmax over rows of 256 (sums NSPLIT partials), warp-shuffle reductions.
// Emits fp16 hi only (stage 5 is now 1-pass).
// ===========================================================================
__global__ __launch_bounds__(256)
void softmax_rows(const float* __restrict__ P, __half* __restrict__ Ah)
{
    const size_t RS = (size_t)BATCH * CCH * CCH;
    const int row = blockIdx.x;
    const int tid = threadIdx.x;
    const int lid = tid & 31;
    const int wrp = tid >> 5;
    const size_t base = (size_t)row * CCH + tid;
    float x = 0.0f;
    #pragma unroll
    for (int s = 0; s < NSPLIT; s++) x += P[s * RS + base];

    __shared__ float red[8];
    float m = x;
    #pragma unroll
    for (int o = 16; o > 0; o >>= 1)
        m = fmaxf(m, __shfl_xor_sync(0xFFFFFFFFu, m, o));
    if (lid == 0) red[wrp] = m;
    __syncthreads();
    float mx = red[0];
    #pragma unroll
    for (int w = 1; w < 8; w++) mx = fmaxf(mx, red[w]);

    const float e = expf(x - mx);
    float sum = e;
    #pragma unroll
    for (int o = 16; o > 0; o >>= 1)
        sum += __shfl_xor_sync(0xFFFFFFFFu, sum, o);
    __syncthreads();
    if (lid == 0) red[wrp] = sum;
    __syncthreads();
    float tot = 0.0f;
    #pragma unroll
    for (int w = 0; w < 8; w++) tot += red[w];

    Ah[base] = __float2half_rn(e / tot);
}

// ===========================================================================
// Launch
// ===========================================================================
extern "C" void kernel_launch(void* const* d_in, const int* in_sizes, int n_in,
                              void* d_out, int out_size)
{
    const float* x1    = (const float*)d_in[0];
    const float* x2    = (const float*)d_in[1];
    const float* w_img = (const float*)d_in[2];
    const float* w_txt = (const float*)d_in[3];
    const float* w_out = (const float*)d_in[4];
    const float* gamma = (const float*)d_in[5];
    float* out = (float*)d_out;

    __half *wih, *wil, *wth, *wtl, *woh, *wol;
    __half *imgh, *imgl, *kvh, *kvl, *kvTh, *tTh, *atth;
    float *part;
    cudaGetSymbolAddress((void**)&wih,  g_wih);
    cudaGetSymbolAddress((void**)&wil,  g_wil);
    cudaGetSymbolAddress((void**)&wth,  g_wth);
    cudaGetSymbolAddress((void**)&wtl,  g_wtl);
    cudaGetSymbolAddress((void**)&woh,  g_woh);
    cudaGetSymbolAddress((void**)&wol,  g_wol);
    cudaGetSymbolAddress((void**)&imgh, g_imgh);
    cudaGetSymbolAddress((void**)&imgl, g_imgl);
    cudaGetSymbolAddress((void**)&kvh,  g_kvh);
    cudaGetSymbolAddress((void**)&kvl,  g_kvl);
    cudaGetSymbolAddress((void**)&kvTh, g_kvTh);
    cudaGetSymbolAddress((void**)&tTh,  g_tTh);
    cudaGetSymbolAddress((void**)&part, g_part);
    cudaGetSymbolAddress((void**)&atth, g_atth);

    cudaFuncSetAttribute(gemm_fused,
                         cudaFuncAttributeMaxDynamicSharedMemorySize, SMEM_F);
    cudaFuncSetAttribute(gemm_mma<false, true,  false, 3>,
                         cudaFuncAttributeMaxDynamicSharedMemorySize, SMEM_TOT);
    cudaFuncSetAttribute(gemm_mma<true,  false, true,  1>,
                         cudaFuncAttributeMaxDynamicSharedMemorySize, SMEM_TOT);
    cudaFuncSetAttribute(gemm_mma<false, true,  false, 1>,
                         cudaFuncAttributeMaxDynamicSharedMemorySize, SMEM_TOT);

    // 0) all weight splits in one launch
    split_w3<<<(NW1 + NW2 + NW3 + 255) / 256, 256>>>(
        w_img, w_txt, w_out, wih, wil, wth, wtl, woh, wol);

    // 1+2) img & kv projections, fused transpose+split, one launch
    gemm_fused<<<dim3(32, 2, 32), 256, SMEM_F>>>(
        wih, wil, x1, imgh, imgl,
        wth, wtl, x2, kvh, kvl, kvTh);

    // 3) logits partials (3-pass, split-K=8)
    gemm_mma<false, true, false, 3><<<dim3(2, 2, 16 * NSPLIT), 256, SMEM_TOT>>>(
        imgh, imgl, kvh, kvl, part, nullptr, nullptr, nullptr, nullptr,
        NSP / NSPLIT, 4096, 4096, 256, 0,
        256L * 4096, 256L * 4096, 256L * 256, 0L, NSPLIT);

    // 4) softmax (hi only)
    softmax_rows<<<BATCH * CCH, 256>>>(part, atth);

    // 5) tT[n,c] = gamma*(attn @ kvT) + (imgh+imgl)  (1-pass, 6-stage)
    gemm_mma<true, false, true, 1><<<dim3(32, 2, 16), 256, SMEM_TOT>>>(
        atth, nullptr, kvTh, nullptr, nullptr, tTh, imgh, imgl, gamma,
        256, 256, 256, 4096, 256,
        256L * 256, 4096L * 256, 256L * 4096, 4096L * 256, 1);

    // 6) out = w_out @ tT  (1-pass, 6-stage)
    gemm_mma<false, true, false, 1><<<dim3(32, 4, 16), 256, SMEM_TOT>>>(
        woh, nullptr, tTh, nullptr, out, nullptr, nullptr, nullptr, nullptr,
        256, 256, 256, 4096, 0,
        0L, 4096L * 256, 512L * 4096, 0L, 1);
}